// round 1
// baseline (speedup 1.0000x reference)
#include <cuda_runtime.h>

#define D_MODEL 1024
#define NHEAD   16
#define DKH     64
#define BATCH   4
#define SEQ     2048
#define MTOT    (BATCH*SEQ)   // 8192

// Scratch: projected Q/K/V and attention output (concat), 33.5 MB each.
__device__ float g_Qp[(size_t)MTOT * D_MODEL];
__device__ float g_Kp[(size_t)MTOT * D_MODEL];
__device__ float g_Vp[(size_t)MTOT * D_MODEL];
__device__ float g_Ct[(size_t)MTOT * D_MODEL];

// ======================================================================
// SGEMM (NT): C[M,N] = A[M,K] * B[N,K]^T   (both row-major, K-major access)
// 128x128 tile, BK=16, 256 threads, 8x8 micro-tile per thread.
// ======================================================================
#define BM 128
#define BN 128
#define BKK 16
#define LDA 132   // 128 + 4 pad: conflict-free transposed stores & aligned float4 reads

__global__ __launch_bounds__(256) void sgemm_nt(
    const float* __restrict__ A, const float* __restrict__ B,
    float* __restrict__ C, int M, int N, int K)
{
    __shared__ float As[BKK][LDA];
    __shared__ float Bs[BKK][LDA];
    const int tid = threadIdx.x;
    const int tx = tid & 15, ty = tid >> 4;
    const int m0 = blockIdx.y * BM, n0 = blockIdx.x * BN;

    float acc[8][8];
    #pragma unroll
    for (int i = 0; i < 8; i++)
        #pragma unroll
        for (int j = 0; j < 8; j++) acc[i][j] = 0.f;

    const int ra = tid >> 2;        // 0..63
    const int ca = (tid & 3) * 4;   // 0,4,8,12
    const float* Ap = A + (size_t)(m0 + ra) * K + ca;
    const float* Bp = B + (size_t)(n0 + ra) * K + ca;

    for (int k0 = 0; k0 < K; k0 += BKK) {
        float4 a0 = *(const float4*)Ap;
        float4 a1 = *(const float4*)(Ap + (size_t)64 * K);
        float4 b0 = *(const float4*)Bp;
        float4 b1 = *(const float4*)(Bp + (size_t)64 * K);
        As[ca+0][ra]    = a0.x; As[ca+1][ra]    = a0.y; As[ca+2][ra]    = a0.z; As[ca+3][ra]    = a0.w;
        As[ca+0][ra+64] = a1.x; As[ca+1][ra+64] = a1.y; As[ca+2][ra+64] = a1.z; As[ca+3][ra+64] = a1.w;
        Bs[ca+0][ra]    = b0.x; Bs[ca+1][ra]    = b0.y; Bs[ca+2][ra]    = b0.z; Bs[ca+3][ra]    = b0.w;
        Bs[ca+0][ra+64] = b1.x; Bs[ca+1][ra+64] = b1.y; Bs[ca+2][ra+64] = b1.z; Bs[ca+3][ra+64] = b1.w;
        __syncthreads();
        #pragma unroll
        for (int k = 0; k < BKK; k++) {
            float a[8], b[8];
            float4 t;
            t = *(const float4*)&As[k][ty*8];   a[0]=t.x; a[1]=t.y; a[2]=t.z; a[3]=t.w;
            t = *(const float4*)&As[k][ty*8+4]; a[4]=t.x; a[5]=t.y; a[6]=t.z; a[7]=t.w;
            t = *(const float4*)&Bs[k][tx*8];   b[0]=t.x; b[1]=t.y; b[2]=t.z; b[3]=t.w;
            t = *(const float4*)&Bs[k][tx*8+4]; b[4]=t.x; b[5]=t.y; b[6]=t.z; b[7]=t.w;
            #pragma unroll
            for (int i = 0; i < 8; i++)
                #pragma unroll
                for (int j = 0; j < 8; j++)
                    acc[i][j] = fmaf(a[i], b[j], acc[i][j]);
        }
        __syncthreads();
        Ap += BKK; Bp += BKK;
    }

    #pragma unroll
    for (int i = 0; i < 8; i++) {
        float* Cp = C + (size_t)(m0 + ty*8 + i) * N + n0 + tx*8;
        *(float4*)Cp       = make_float4(acc[i][0], acc[i][1], acc[i][2], acc[i][3]);
        *(float4*)(Cp + 4) = make_float4(acc[i][4], acc[i][5], acc[i][6], acc[i][7]);
    }
}

// ======================================================================
// Flash attention (fp32, online softmax).
// One block = (batch b, head h, 64 query rows). 256 threads as 16x16 grid,
// each thread owns a 4x4 micro-tile of scores and of the output.
// Q/K stored d-major (transposed) in smem for conflict-free float4 reads.
// P tile overlays the K tile (K is dead once scores are computed).
// ======================================================================
#define BQ  64
#define BKT 64
#define LDP 68   // 64 + 4 pad, keeps float4 alignment
#define FLASH_SMEM ((2*64*LDP + 64*DKH) * sizeof(float))   // 51200 B

__global__ __launch_bounds__(256) void flash_attn(
    const float* __restrict__ Qp, const float* __restrict__ Kp,
    const float* __restrict__ Vp, float* __restrict__ Op)
{
    extern __shared__ float sm[];
    float* QsT = sm;                 // [64 d][LDP q]
    float* KsT = sm + 64 * LDP;      // [64 d][LDP k], reused as Ps[64 q][LDP k]
    float* Vs  = sm + 2 * 64 * LDP;  // [64 k][64 d]

    const int tid = threadIdx.x;
    const int tx = tid & 15, ty = tid >> 4;
    const int b = blockIdx.z, h = blockIdx.y;
    const int q0 = blockIdx.x * BQ;

    const float* Qb = Qp + ((size_t)b * SEQ + q0) * D_MODEL + h * DKH;
    const float* Kb = Kp + (size_t)b * SEQ * D_MODEL + h * DKH;
    const float* Vb = Vp + (size_t)b * SEQ * D_MODEL + h * DKH;

    // Load Q tile transposed, pre-scaled by 1/sqrt(d_k) = 0.125
    {
        const int r = tid >> 2;
        const float* q = Qb + (size_t)r * D_MODEL;
        #pragma unroll
        for (int i = 0; i < 4; i++) {
            int f = (tid & 3) * 4 + i;
            float4 v = *(const float4*)(q + f * 4);
            QsT[(f*4+0)*LDP + r] = v.x * 0.125f;
            QsT[(f*4+1)*LDP + r] = v.y * 0.125f;
            QsT[(f*4+2)*LDP + r] = v.z * 0.125f;
            QsT[(f*4+3)*LDP + r] = v.w * 0.125f;
        }
    }

    float o[4][4];
    float mrow[4], lrow[4];
    #pragma unroll
    for (int i = 0; i < 4; i++) {
        mrow[i] = -1e30f; lrow[i] = 0.f;
        #pragma unroll
        for (int c = 0; c < 4; c++) o[i][c] = 0.f;
    }

    for (int kt = 0; kt < SEQ / BKT; kt++) {
        __syncthreads();   // previous PV done before overwriting KsT/Vs
        {
            const int r = tid >> 2;
            const float* kp = Kb + (size_t)(kt * BKT + r) * D_MODEL;
            const float* vp = Vb + (size_t)(kt * BKT + r) * D_MODEL;
            #pragma unroll
            for (int i = 0; i < 4; i++) {
                int f = (tid & 3) * 4 + i;
                float4 v = *(const float4*)(kp + f * 4);
                KsT[(f*4+0)*LDP + r] = v.x;
                KsT[(f*4+1)*LDP + r] = v.y;
                KsT[(f*4+2)*LDP + r] = v.z;
                KsT[(f*4+3)*LDP + r] = v.w;
                *(float4*)(Vs + r * DKH + f * 4) = *(const float4*)(vp + f * 4);
            }
        }
        __syncthreads();

        // Scores: s[i][j] = (Q/8) . K  for rows ty*4+i, cols tx*4+j
        float s[4][4];
        #pragma unroll
        for (int i = 0; i < 4; i++)
            #pragma unroll
            for (int j = 0; j < 4; j++) s[i][j] = 0.f;

        #pragma unroll 16
        for (int k = 0; k < DKH; k++) {
            float4 qv = *(const float4*)(QsT + k * LDP + ty * 4);
            float4 kv = *(const float4*)(KsT + k * LDP + tx * 4);
            float qa[4] = {qv.x, qv.y, qv.z, qv.w};
            float ka[4] = {kv.x, kv.y, kv.z, kv.w};
            #pragma unroll
            for (int i = 0; i < 4; i++)
                #pragma unroll
                for (int j = 0; j < 4; j++)
                    s[i][j] = fmaf(qa[i], ka[j], s[i][j]);
        }

        // Online softmax per row (16 threads per row: same ty → 16 lanes, shuffle-reduce)
        float p[4][4];
        #pragma unroll
        for (int i = 0; i < 4; i++) {
            float tm = fmaxf(fmaxf(s[i][0], s[i][1]), fmaxf(s[i][2], s[i][3]));
            tm = fmaxf(tm, __shfl_xor_sync(0xffffffffu, tm, 1));
            tm = fmaxf(tm, __shfl_xor_sync(0xffffffffu, tm, 2));
            tm = fmaxf(tm, __shfl_xor_sync(0xffffffffu, tm, 4));
            tm = fmaxf(tm, __shfl_xor_sync(0xffffffffu, tm, 8));
            float mn = fmaxf(mrow[i], tm);
            float corr = __expf(mrow[i] - mn);
            mrow[i] = mn;
            float rs = 0.f;
            #pragma unroll
            for (int j = 0; j < 4; j++) { p[i][j] = __expf(s[i][j] - mn); rs += p[i][j]; }
            rs += __shfl_xor_sync(0xffffffffu, rs, 1);
            rs += __shfl_xor_sync(0xffffffffu, rs, 2);
            rs += __shfl_xor_sync(0xffffffffu, rs, 4);
            rs += __shfl_xor_sync(0xffffffffu, rs, 8);
            lrow[i] = lrow[i] * corr + rs;
            #pragma unroll
            for (int c = 0; c < 4; c++) o[i][c] *= corr;
        }

        __syncthreads();   // everyone done reading KsT
        #pragma unroll
        for (int i = 0; i < 4; i++)
            *(float4*)(KsT + (ty*4+i)*LDP + tx*4) =
                make_float4(p[i][0], p[i][1], p[i][2], p[i][3]);
        __syncthreads();

        // PV: o[i][c] += P[row, j] * V[j, col]
        #pragma unroll 8
        for (int j = 0; j < BKT; j++) {
            float4 vv = *(const float4*)(Vs + j * DKH + tx * 4);
            float va[4] = {vv.x, vv.y, vv.z, vv.w};
            #pragma unroll
            for (int i = 0; i < 4; i++) {
                float pv = KsT[(ty*4+i)*LDP + j];   // broadcast across tx
                #pragma unroll
                for (int c = 0; c < 4; c++)
                    o[i][c] = fmaf(pv, va[c], o[i][c]);
            }
        }
    }

    // Normalize and write (concat layout [B,S,H*dk] directly)
    float* Ob = Op + ((size_t)b * SEQ + q0) * D_MODEL + h * DKH;
    #pragma unroll
    for (int i = 0; i < 4; i++) {
        float inv = 1.f / lrow[i];
        *(float4*)(Ob + (size_t)(ty*4+i) * D_MODEL + tx*4) =
            make_float4(o[i][0]*inv, o[i][1]*inv, o[i][2]*inv, o[i][3]*inv);
    }
}

// ======================================================================
extern "C" void kernel_launch(void* const* d_in, const int* in_sizes, int n_in,
                              void* d_out, int out_size)
{
    (void)in_sizes; (void)n_in; (void)out_size;
    const float* Q_in = (const float*)d_in[0];
    const float* K_in = (const float*)d_in[1];
    const float* V_in = (const float*)d_in[2];
    const float* W_q  = (const float*)d_in[3];
    const float* W_k  = (const float*)d_in[4];
    const float* W_v  = (const float*)d_in[5];
    const float* W_o  = (const float*)d_in[6];
    float* out = (float*)d_out;

    float *Qp, *Kp, *Vp, *Ct;
    cudaGetSymbolAddress((void**)&Qp, g_Qp);
    cudaGetSymbolAddress((void**)&Kp, g_Kp);
    cudaGetSymbolAddress((void**)&Vp, g_Vp);
    cudaGetSymbolAddress((void**)&Ct, g_Ct);

    cudaFuncSetAttribute(flash_attn, cudaFuncAttributeMaxDynamicSharedMemorySize,
                         (int)FLASH_SMEM);

    dim3 gproj(D_MODEL / BN, MTOT / BM);   // (8, 64)
    sgemm_nt<<<gproj, 256>>>(Q_in, W_q, Qp, MTOT, D_MODEL, D_MODEL);
    sgemm_nt<<<gproj, 256>>>(K_in, W_k, Kp, MTOT, D_MODEL, D_MODEL);
    sgemm_nt<<<gproj, 256>>>(V_in, W_v, Vp, MTOT, D_MODEL, D_MODEL);

    flash_attn<<<dim3(SEQ/BQ, NHEAD, BATCH), 256, FLASH_SMEM>>>(Qp, Kp, Vp, Ct);

    sgemm_nt<<<gproj, 256>>>(Ct, W_o, out, MTOT, D_MODEL, D_MODEL);
}

// round 3
// speedup vs baseline: 1.3152x; 1.3152x over previous
#include <cuda_runtime.h>
#include <cstdint>

#define D_MODEL 1024
#define NHEAD   16
#define DKH     64
#define BATCH   4
#define SEQ     2048
#define MTOT    (BATCH*SEQ)   // 8192

// Scratch: projected Q/K/V and attention output (concat), 33.5 MB each.
__device__ float g_Qp[(size_t)MTOT * D_MODEL];
__device__ float g_Kp[(size_t)MTOT * D_MODEL];
__device__ float g_Vp[(size_t)MTOT * D_MODEL];
__device__ float g_Ct[(size_t)MTOT * D_MODEL];

__device__ __forceinline__ uint32_t tf32_rn(float x) {
    uint32_t u;
    asm("cvt.rn.tf32.f32 %0, %1;" : "=r"(u) : "f"(x));
    return u;
}

__device__ __forceinline__ void mma_tf32(float c[4], const uint32_t a[4], const uint32_t b[2]) {
    asm volatile(
        "mma.sync.aligned.m16n8k8.row.col.f32.tf32.tf32.f32 "
        "{%0,%1,%2,%3}, {%4,%5,%6,%7}, {%8,%9}, {%0,%1,%2,%3};"
        : "+f"(c[0]), "+f"(c[1]), "+f"(c[2]), "+f"(c[3])
        : "r"(a[0]), "r"(a[1]), "r"(a[2]), "r"(a[3]), "r"(b[0]), "r"(b[1]));
}

// ======================================================================
// tf32 tensor-core GEMM (NT): C[M,N] = A[M,K] * B[N,K]^T
// CTA tile 128x128, BK=16, 256 threads = 8 warps (2m x 4n), warp tile 64x32.
// Smem stored transposed (k-major rows) as tf32 bits; RN rounding at STS.
// ======================================================================
#define BM 128
#define BN 128
#define BKK 16
#define LDA 132   // pad: conflict-bounded transposed stores / fragment loads

__global__ __launch_bounds__(256) void gemm_tf32mma(
    const float* __restrict__ A, const float* __restrict__ B,
    float* __restrict__ C, int M, int N, int K)
{
    __shared__ uint32_t As[2][BKK][LDA];
    __shared__ uint32_t Bs[2][BKK][LDA];

    const int tid  = threadIdx.x;
    const int lane = tid & 31;
    const int wid  = tid >> 5;
    const int wm = (wid & 1) * 64;    // warp m-offset within CTA tile
    const int wn = (wid >> 1) * 32;   // warp n-offset
    const int m0 = blockIdx.y * BM, n0 = blockIdx.x * BN;

    float c[4][4][4];
    #pragma unroll
    for (int i = 0; i < 4; i++)
        #pragma unroll
        for (int j = 0; j < 4; j++)
            #pragma unroll
            for (int r = 0; r < 4; r++) c[i][j][r] = 0.f;

    // loaders: 256 threads, rows ra & ra+64, 16B chunk ca
    const int ra = tid >> 2;         // 0..63
    const int ca = (tid & 3) * 4;    // 0,4,8,12
    const float* Ap = A + (size_t)(m0 + ra) * K + ca;
    const float* Bp = B + (size_t)(n0 + ra) * K + ca;

    float4 va0, va1, vb0, vb1;
    auto ldg = [&](int kt) {
        const float* ap = Ap + kt * BKK;
        const float* bp = Bp + kt * BKK;
        va0 = __ldg((const float4*)ap);
        va1 = __ldg((const float4*)(ap + (size_t)64 * K));
        vb0 = __ldg((const float4*)bp);
        vb1 = __ldg((const float4*)(bp + (size_t)64 * K));
    };
    auto sts = [&](int buf) {
        #pragma unroll
        for (int j = 0; j < 4; j++) {
            As[buf][ca+j][ra]    = tf32_rn(j==0?va0.x:j==1?va0.y:j==2?va0.z:va0.w);
            As[buf][ca+j][ra+64] = tf32_rn(j==0?va1.x:j==1?va1.y:j==2?va1.z:va1.w);
            Bs[buf][ca+j][ra]    = tf32_rn(j==0?vb0.x:j==1?vb0.y:j==2?vb0.z:vb0.w);
            Bs[buf][ca+j][ra+64] = tf32_rn(j==0?vb1.x:j==1?vb1.y:j==2?vb1.z:vb1.w);
        }
    };
    auto compute = [&](int buf) {
        #pragma unroll
        for (int s = 0; s < 2; s++) {
            const int kk = s * 8 + (lane & 3);
            const int mr = wm + (lane >> 2);
            const int nc = wn + (lane >> 2);
            uint32_t a[4][4], b[4][2];
            #pragma unroll
            for (int mt = 0; mt < 4; mt++) {
                a[mt][0] = As[buf][kk]  [mr + mt*16];
                a[mt][1] = As[buf][kk]  [mr + mt*16 + 8];
                a[mt][2] = As[buf][kk+4][mr + mt*16];
                a[mt][3] = As[buf][kk+4][mr + mt*16 + 8];
            }
            #pragma unroll
            for (int nt = 0; nt < 4; nt++) {
                b[nt][0] = Bs[buf][kk]  [nc + nt*8];
                b[nt][1] = Bs[buf][kk+4][nc + nt*8];
            }
            #pragma unroll
            for (int mt = 0; mt < 4; mt++)
                #pragma unroll
                for (int nt = 0; nt < 4; nt++)
                    mma_tf32(c[mt][nt], a[mt], b[nt]);
        }
    };

    const int NKT = K / BKK;
    ldg(0);
    sts(0);
    __syncthreads();

    for (int kt = 0; kt < NKT; kt++) {
        if (kt + 1 < NKT) ldg(kt + 1);
        compute(kt & 1);
        if (kt + 1 < NKT) {
            __syncthreads();
            sts((kt + 1) & 1);
            __syncthreads();
        }
    }

    // epilogue: fragment c -> C
    const int mbase = m0 + wm + (lane >> 2);
    const int nbase = n0 + wn + (lane & 3) * 2;
    #pragma unroll
    for (int mt = 0; mt < 4; mt++) {
        #pragma unroll
        for (int nt = 0; nt < 4; nt++) {
            float* p0 = C + (size_t)(mbase + mt*16)     * N + nbase + nt*8;
            float* p1 = C + (size_t)(mbase + mt*16 + 8) * N + nbase + nt*8;
            *(float2*)p0 = make_float2(c[mt][nt][0], c[mt][nt][1]);
            *(float2*)p1 = make_float2(c[mt][nt][2], c[mt][nt][3]);
        }
    }
}

// ======================================================================
// Flash attention (fp32, online softmax) — unchanged (known good).
// ======================================================================
#define BQ  64
#define BKT 64
#define LDP 68
#define FLASH_SMEM ((2*64*LDP + 64*DKH) * sizeof(float))   // 51200 B

__global__ __launch_bounds__(256) void flash_attn(
    const float* __restrict__ Qp, const float* __restrict__ Kp,
    const float* __restrict__ Vp, float* __restrict__ Op)
{
    extern __shared__ float sm[];
    float* QsT = sm;
    float* KsT = sm + 64 * LDP;
    float* Vs  = sm + 2 * 64 * LDP;

    const int tid = threadIdx.x;
    const int tx = tid & 15, ty = tid >> 4;
    const int b = blockIdx.z, h = blockIdx.y;
    const int q0 = blockIdx.x * BQ;

    const float* Qb = Qp + ((size_t)b * SEQ + q0) * D_MODEL + h * DKH;
    const float* Kb = Kp + (size_t)b * SEQ * D_MODEL + h * DKH;
    const float* Vb = Vp + (size_t)b * SEQ * D_MODEL + h * DKH;

    {
        const int r = tid >> 2;
        const float* q = Qb + (size_t)r * D_MODEL;
        #pragma unroll
        for (int i = 0; i < 4; i++) {
            int f = (tid & 3) * 4 + i;
            float4 v = *(const float4*)(q + f * 4);
            QsT[(f*4+0)*LDP + r] = v.x * 0.125f;
            QsT[(f*4+1)*LDP + r] = v.y * 0.125f;
            QsT[(f*4+2)*LDP + r] = v.z * 0.125f;
            QsT[(f*4+3)*LDP + r] = v.w * 0.125f;
        }
    }

    float o[4][4];
    float mrow[4], lrow[4];
    #pragma unroll
    for (int i = 0; i < 4; i++) {
        mrow[i] = -1e30f; lrow[i] = 0.f;
        #pragma unroll
        for (int c = 0; c < 4; c++) o[i][c] = 0.f;
    }

    for (int kt = 0; kt < SEQ / BKT; kt++) {
        __syncthreads();
        {
            const int r = tid >> 2;
            const float* kp = Kb + (size_t)(kt * BKT + r) * D_MODEL;
            const float* vp = Vb + (size_t)(kt * BKT + r) * D_MODEL;
            #pragma unroll
            for (int i = 0; i < 4; i++) {
                int f = (tid & 3) * 4 + i;
                float4 v = *(const float4*)(kp + f * 4);
                KsT[(f*4+0)*LDP + r] = v.x;
                KsT[(f*4+1)*LDP + r] = v.y;
                KsT[(f*4+2)*LDP + r] = v.z;
                KsT[(f*4+3)*LDP + r] = v.w;
                *(float4*)(Vs + r * DKH + f * 4) = *(const float4*)(vp + f * 4);
            }
        }
        __syncthreads();

        float s[4][4];
        #pragma unroll
        for (int i = 0; i < 4; i++)
            #pragma unroll
            for (int j = 0; j < 4; j++) s[i][j] = 0.f;

        #pragma unroll 16
        for (int k = 0; k < DKH; k++) {
            float4 qv = *(const float4*)(QsT + k * LDP + ty * 4);
            float4 kv = *(const float4*)(KsT + k * LDP + tx * 4);
            float qa[4] = {qv.x, qv.y, qv.z, qv.w};
            float ka[4] = {kv.x, kv.y, kv.z, kv.w};
            #pragma unroll
            for (int i = 0; i < 4; i++)
                #pragma unroll
                for (int j = 0; j < 4; j++)
                    s[i][j] = fmaf(qa[i], ka[j], s[i][j]);
        }

        float p[4][4];
        #pragma unroll
        for (int i = 0; i < 4; i++) {
            float tm = fmaxf(fmaxf(s[i][0], s[i][1]), fmaxf(s[i][2], s[i][3]));
            tm = fmaxf(tm, __shfl_xor_sync(0xffffffffu, tm, 1));
            tm = fmaxf(tm, __shfl_xor_sync(0xffffffffu, tm, 2));
            tm = fmaxf(tm, __shfl_xor_sync(0xffffffffu, tm, 4));
            tm = fmaxf(tm, __shfl_xor_sync(0xffffffffu, tm, 8));
            float mn = fmaxf(mrow[i], tm);
            float corr = __expf(mrow[i] - mn);
            mrow[i] = mn;
            float rs = 0.f;
            #pragma unroll
            for (int j = 0; j < 4; j++) { p[i][j] = __expf(s[i][j] - mn); rs += p[i][j]; }
            rs += __shfl_xor_sync(0xffffffffu, rs, 1);
            rs += __shfl_xor_sync(0xffffffffu, rs, 2);
            rs += __shfl_xor_sync(0xffffffffu, rs, 4);
            rs += __shfl_xor_sync(0xffffffffu, rs, 8);
            lrow[i] = lrow[i] * corr + rs;
            #pragma unroll
            for (int c = 0; c < 4; c++) o[i][c] *= corr;
        }

        __syncthreads();
        #pragma unroll
        for (int i = 0; i < 4; i++)
            *(float4*)(KsT + (ty*4+i)*LDP + tx*4) =
                make_float4(p[i][0], p[i][1], p[i][2], p[i][3]);
        __syncthreads();

        #pragma unroll 8
        for (int j = 0; j < BKT; j++) {
            float4 vv = *(const float4*)(Vs + j * DKH + tx * 4);
            float va[4] = {vv.x, vv.y, vv.z, vv.w};
            #pragma unroll
            for (int i = 0; i < 4; i++) {
                float pv = KsT[(ty*4+i)*LDP + j];
                #pragma unroll
                for (int c = 0; c < 4; c++)
                    o[i][c] = fmaf(pv, va[c], o[i][c]);
            }
        }
    }

    float* Ob = Op + ((size_t)b * SEQ + q0) * D_MODEL + h * DKH;
    #pragma unroll
    for (int i = 0; i < 4; i++) {
        float inv = 1.f / lrow[i];
        *(float4*)(Ob + (size_t)(ty*4+i) * D_MODEL + tx*4) =
            make_float4(o[i][0]*inv, o[i][1]*inv, o[i][2]*inv, o[i][3]*inv);
    }
}

// ======================================================================
extern "C" void kernel_launch(void* const* d_in, const int* in_sizes, int n_in,
                              void* d_out, int out_size)
{
    (void)in_sizes; (void)n_in; (void)out_size;
    const float* Q_in = (const float*)d_in[0];
    const float* K_in = (const float*)d_in[1];
    const float* V_in = (const float*)d_in[2];
    const float* W_q  = (const float*)d_in[3];
    const float* W_k  = (const float*)d_in[4];
    const float* W_v  = (const float*)d_in[5];
    const float* W_o  = (const float*)d_in[6];
    float* out = (float*)d_out;

    float *Qp, *Kp, *Vp, *Ct;
    cudaGetSymbolAddress((void**)&Qp, g_Qp);
    cudaGetSymbolAddress((void**)&Kp, g_Kp);
    cudaGetSymbolAddress((void**)&Vp, g_Vp);
    cudaGetSymbolAddress((void**)&Ct, g_Ct);

    cudaFuncSetAttribute(flash_attn, cudaFuncAttributeMaxDynamicSharedMemorySize,
                         (int)FLASH_SMEM);

    dim3 gproj(D_MODEL / BN, MTOT / BM);   // (8, 64)
    gemm_tf32mma<<<gproj, 256>>>(Q_in, W_q, Qp, MTOT, D_MODEL, D_MODEL);
    gemm_tf32mma<<<gproj, 256>>>(K_in, W_k, Kp, MTOT, D_MODEL, D_MODEL);
    gemm_tf32mma<<<gproj, 256>>>(V_in, W_v, Vp, MTOT, D_MODEL, D_MODEL);

    flash_attn<<<dim3(SEQ/BQ, NHEAD, BATCH), 256, FLASH_SMEM>>>(Qp, Kp, Vp, Ct);

    gemm_tf32mma<<<gproj, 256>>>(Ct, W_o, out, MTOT, D_MODEL, D_MODEL);
}

// round 4
// speedup vs baseline: 3.0774x; 2.3399x over previous
#include <cuda_runtime.h>
#include <cstdint>

#define D_MODEL 1024
#define NHEAD   16
#define DKH     64
#define BATCH   4
#define SEQ     2048
#define MTOT    (BATCH*SEQ)   // 8192

// Scratch
__device__ float g_Qp[(size_t)MTOT * D_MODEL];
__device__ float g_Kp[(size_t)MTOT * D_MODEL];
__device__ float g_Vp[(size_t)MTOT * D_MODEL];
__device__ float g_Ct[(size_t)MTOT * D_MODEL];
// tf32-RN pre-rounded copies of inputs (cp.async path cannot convert)
__device__ float g_rQ[(size_t)MTOT * D_MODEL];
__device__ float g_rK[(size_t)MTOT * D_MODEL];
__device__ float g_rV[(size_t)MTOT * D_MODEL];
__device__ float g_rWq[(size_t)D_MODEL * D_MODEL];
__device__ float g_rWk[(size_t)D_MODEL * D_MODEL];
__device__ float g_rWv[(size_t)D_MODEL * D_MODEL];
__device__ float g_rWo[(size_t)D_MODEL * D_MODEL];

// ---------------- PTX helpers ----------------
__device__ __forceinline__ float tf32f(float x) {
    uint32_t u;
    asm("cvt.rn.tf32.f32 %0, %1;" : "=r"(u) : "f"(x));
    return __uint_as_float(u);
}
__device__ __forceinline__ uint32_t smem_u32(const void* p) {
    uint32_t a;
    asm("{ .reg .u64 t; cvta.to.shared.u64 t, %1; cvt.u32.u64 %0, t; }" : "=r"(a) : "l"(p));
    return a;
}
__device__ __forceinline__ void mma_tf32(float c[4], const uint32_t a[4], const uint32_t b[2]) {
    asm volatile(
        "mma.sync.aligned.m16n8k8.row.col.f32.tf32.tf32.f32 "
        "{%0,%1,%2,%3}, {%4,%5,%6,%7}, {%8,%9}, {%0,%1,%2,%3};"
        : "+f"(c[0]), "+f"(c[1]), "+f"(c[2]), "+f"(c[3])
        : "r"(a[0]), "r"(a[1]), "r"(a[2]), "r"(a[3]), "r"(b[0]), "r"(b[1]));
}
#define LDSM_X4(r0,r1,r2,r3,addr) \
    asm volatile("ldmatrix.sync.aligned.m8n8.x4.shared.b16 {%0,%1,%2,%3}, [%4];" \
        : "=r"(r0),"=r"(r1),"=r"(r2),"=r"(r3) : "r"(addr))
#define CP16(sa, ga)  asm volatile("cp.async.cg.shared.global [%0], [%1], 16;" :: "r"(sa), "l"(ga))
#define CP_COMMIT()   asm volatile("cp.async.commit_group;" ::: "memory")
#define CP_WAIT(n)    asm volatile("cp.async.wait_group %0;" :: "n"(n) : "memory")

// ---------------- tf32-RN rounding pass ----------------
__global__ void round_tf32_k(const float* __restrict__ in, float* __restrict__ out, int n4)
{
    int i = blockIdx.x * blockDim.x + threadIdx.x;
    if (i < n4) {
        float4 v = ((const float4*)in)[i];
        v.x = tf32f(v.x); v.y = tf32f(v.y); v.z = tf32f(v.z); v.w = tf32f(v.w);
        ((float4*)out)[i] = v;
    }
}

// ======================================================================
// GEMM (NT): C[8192,1024] = A[8192,1024] * B[1024,1024]^T
// 128x128 CTA tile, BK=32, 3-stage cp.async, ldmatrix fragments.
// Inputs MUST be tf32-RN pre-rounded. roundC: round C to tf32 on store.
// ======================================================================
#define GEMM_SMEM (3 * 32768)

__global__ __launch_bounds__(256, 2) void gemm_tc(
    const float* __restrict__ A, const float* __restrict__ B,
    float* __restrict__ C, int roundC)
{
    extern __shared__ char sm[];
    const uint32_t sbase = smem_u32(sm);
    const int tid = threadIdx.x, lane = tid & 31, wid = tid >> 5;
    const int wm = (wid & 1) * 64, wn = (wid >> 1) * 32;
    const int m0 = blockIdx.y * 128, n0 = blockIdx.x * 128;

    float c[4][4][4];
    #pragma unroll
    for (int i = 0; i < 4; i++)
        #pragma unroll
        for (int j = 0; j < 4; j++)
            #pragma unroll
            for (int r = 0; r < 4; r++) c[i][j][r] = 0.f;

    auto issue = [&](int kt, int buf) {
        #pragma unroll
        for (int i = 0; i < 4; i++) {
            const int id = tid + 256 * i;
            const int row = id >> 3, cx = id & 7;
            const uint32_t off = row * 128 + (((uint32_t)(cx ^ (row & 7))) << 4);
            const float* ga = A + (size_t)(m0 + row) * 1024 + kt * 32 + cx * 4;
            const float* gb = B + (size_t)(n0 + row) * 1024 + kt * 32 + cx * 4;
            CP16(sbase + buf * 32768 + off, ga);
            CP16(sbase + buf * 32768 + 16384 + off, gb);
        }
        CP_COMMIT();
    };

    issue(0, 0);
    issue(1, 1);

    const int NKT = 32;
    for (int kt = 0; kt < NKT; kt++) {
        if (kt + 1 < NKT) { CP_WAIT(1); } else { CP_WAIT(0); }
        __syncthreads();
        if (kt + 2 < NKT) issue(kt + 2, (kt + 2) % 3);

        const uint32_t abase = sbase + (kt % 3) * 32768;
        const uint32_t bbase = abase + 16384;
        #pragma unroll
        for (int ks = 0; ks < 4; ks++) {
            uint32_t a[4][4], b[4][2];
            #pragma unroll
            for (int mt = 0; mt < 4; mt++) {
                const int row = wm + mt * 16 + (lane & 7) + ((lane >> 3) & 1) * 8;
                const int ch  = ks * 2 + (lane >> 4);
                const uint32_t ad = abase + row * 128 + (((uint32_t)(ch ^ (row & 7))) << 4);
                LDSM_X4(a[mt][0], a[mt][1], a[mt][2], a[mt][3], ad);
            }
            #pragma unroll
            for (int p = 0; p < 2; p++) {
                const int row = wn + p * 16 + (lane & 7) + (lane >> 4) * 8;
                const int ch  = ks * 2 + ((lane >> 3) & 1);
                const uint32_t bd = bbase + row * 128 + (((uint32_t)(ch ^ (row & 7))) << 4);
                LDSM_X4(b[2*p][0], b[2*p][1], b[2*p+1][0], b[2*p+1][1], bd);
            }
            #pragma unroll
            for (int mt = 0; mt < 4; mt++)
                #pragma unroll
                for (int nt = 0; nt < 4; nt++)
                    mma_tf32(c[mt][nt], a[mt], b[nt]);
        }
    }

    const int mbase = m0 + wm + (lane >> 2);
    const int nbase = n0 + wn + (lane & 3) * 2;
    #pragma unroll
    for (int mt = 0; mt < 4; mt++) {
        #pragma unroll
        for (int nt = 0; nt < 4; nt++) {
            float v0 = c[mt][nt][0], v1 = c[mt][nt][1];
            float v2 = c[mt][nt][2], v3 = c[mt][nt][3];
            if (roundC) { v0 = tf32f(v0); v1 = tf32f(v1); v2 = tf32f(v2); v3 = tf32f(v3); }
            float* p0 = C + (size_t)(mbase + mt*16)     * 1024 + nbase + nt*8;
            float* p1 = C + (size_t)(mbase + mt*16 + 8) * 1024 + nbase + nt*8;
            *(float2*)p0 = make_float2(v0, v1);
            *(float2*)p1 = make_float2(v2, v3);
        }
    }
}

// ======================================================================
// Flash attention on tensor cores (tf32 MMA, fp32 softmax).
// 128 threads = 4 warps; each warp owns 16 q-rows. BQ=64, BKT=64, d=64.
// Smem rows padded to 68 floats (272B): conflict-free ldmatrix, no swizzle.
// P overlays the K tile. Inputs are tf32-pre-rounded by gemm_tc epilogue.
// ======================================================================
#define FROW 68
#define FLASH_SMEM (3 * 64 * FROW * 4)   // Qs | Ks(=Ps) | VsT = 52224 B

__global__ __launch_bounds__(128) void flash_tc(
    const float* __restrict__ Qp, const float* __restrict__ Kp,
    const float* __restrict__ Vp, float* __restrict__ Op)
{
    extern __shared__ float fs[];
    const uint32_t sb = smem_u32(fs);
    const uint32_t Qb_s = sb;
    const uint32_t Kb_s = sb + 64 * FROW * 4;
    const uint32_t Vb_s = sb + 2 * 64 * FROW * 4;
    float* Qs = fs;
    float* Ks = fs + 64 * FROW;
    float* Vt = fs + 2 * 64 * FROW;

    const int tid = threadIdx.x, lane = tid & 31, w = tid >> 5;
    const int b = blockIdx.z, h = blockIdx.y;
    const int q0 = blockIdx.x * 64;

    const float* Qg = Qp + ((size_t)b * SEQ + q0) * D_MODEL + h * DKH;
    const float* Kg = Kp + (size_t)b * SEQ * D_MODEL + h * DKH;
    const float* Vg = Vp + (size_t)b * SEQ * D_MODEL + h * DKH;

    // Load Q (scaled by 1/8; tf32-exact since input is pre-rounded)
    #pragma unroll
    for (int i = 0; i < 8; i++) {
        const int id = tid + 128 * i;
        const int row = id >> 4, ch = id & 15;
        float4 v = *(const float4*)(Qg + (size_t)row * D_MODEL + ch * 4);
        v.x *= 0.125f; v.y *= 0.125f; v.z *= 0.125f; v.w *= 0.125f;
        *(float4*)(Qs + row * FROW + ch * 4) = v;
    }

    float o[8][4];
    #pragma unroll
    for (int nt = 0; nt < 8; nt++)
        #pragma unroll
        for (int j = 0; j < 4; j++) o[nt][j] = 0.f;
    float m0r = -1e30f, m1r = -1e30f, l0r = 0.f, l1r = 0.f;

    // Per-lane ldmatrix row offsets (bytes), constant across iterations
    const uint32_t arow = (uint32_t)(w * 16 + (lane & 7) + ((lane >> 3) & 1) * 8) * (FROW * 4);
    const uint32_t ach  = (uint32_t)(lane >> 4) * 16;          // + ks*32
    uint32_t brow[4];
    #pragma unroll
    for (int p = 0; p < 4; p++)
        brow[p] = (uint32_t)(p * 16 + (lane & 7) + (lane >> 4) * 8) * (FROW * 4);
    const uint32_t bch = (uint32_t)((lane >> 3) & 1) * 16;     // + ks*32

    const int vs = tid >> 1;          // seq row handled for V transpose
    const int vh = tid & 1;           // which 32-d half

    for (int kt = 0; kt < SEQ / 64; kt++) {
        __syncthreads();   // prev PV done (Ps=Ks, Vt); safe to overwrite
        #pragma unroll
        for (int i = 0; i < 8; i++) {
            const int id = tid + 128 * i;
            const int row = id >> 4, ch = id & 15;
            *(float4*)(Ks + row * FROW + ch * 4) =
                *(const float4*)(Kg + (size_t)(kt * 64 + row) * D_MODEL + ch * 4);
        }
        #pragma unroll
        for (int i = 0; i < 8; i++) {
            float4 v = *(const float4*)(Vg + (size_t)(kt * 64 + vs) * D_MODEL + (vh * 8 + i) * 4);
            const int d0 = (vh * 8 + i) * 4;
            Vt[(d0 + 0) * FROW + vs] = v.x;
            Vt[(d0 + 1) * FROW + vs] = v.y;
            Vt[(d0 + 2) * FROW + vs] = v.z;
            Vt[(d0 + 3) * FROW + vs] = v.w;
        }
        __syncthreads();

        // S = Q K^T  (m16 x n64, k=64)
        float sf[8][4];
        #pragma unroll
        for (int nt = 0; nt < 8; nt++)
            #pragma unroll
            for (int j = 0; j < 4; j++) sf[nt][j] = 0.f;

        #pragma unroll
        for (int ks = 0; ks < 8; ks++) {
            uint32_t aq[4], bk[8][2];
            LDSM_X4(aq[0], aq[1], aq[2], aq[3], Qb_s + arow + ach + ks * 32);
            #pragma unroll
            for (int p = 0; p < 4; p++)
                LDSM_X4(bk[2*p][0], bk[2*p][1], bk[2*p+1][0], bk[2*p+1][1],
                        Kb_s + brow[p] + bch + ks * 32);
            #pragma unroll
            for (int nt = 0; nt < 8; nt++)
                mma_tf32(sf[nt], aq, bk[nt]);
        }

        // Online softmax (rows r = lane>>2 and r+8; quad lanes share a row)
        float mn0 = m0r, mn1 = m1r;
        #pragma unroll
        for (int nt = 0; nt < 8; nt++) {
            mn0 = fmaxf(mn0, fmaxf(sf[nt][0], sf[nt][1]));
            mn1 = fmaxf(mn1, fmaxf(sf[nt][2], sf[nt][3]));
        }
        mn0 = fmaxf(mn0, __shfl_xor_sync(0xffffffffu, mn0, 1));
        mn0 = fmaxf(mn0, __shfl_xor_sync(0xffffffffu, mn0, 2));
        mn1 = fmaxf(mn1, __shfl_xor_sync(0xffffffffu, mn1, 1));
        mn1 = fmaxf(mn1, __shfl_xor_sync(0xffffffffu, mn1, 2));
        const float corr0 = __expf(m0r - mn0);
        const float corr1 = __expf(m1r - mn1);
        m0r = mn0; m1r = mn1;

        float rs0 = 0.f, rs1 = 0.f;
        #pragma unroll
        for (int nt = 0; nt < 8; nt++) {
            sf[nt][0] = __expf(sf[nt][0] - mn0);
            sf[nt][1] = __expf(sf[nt][1] - mn0);
            sf[nt][2] = __expf(sf[nt][2] - mn1);
            sf[nt][3] = __expf(sf[nt][3] - mn1);
            rs0 += sf[nt][0] + sf[nt][1];
            rs1 += sf[nt][2] + sf[nt][3];
        }
        rs0 += __shfl_xor_sync(0xffffffffu, rs0, 1);
        rs0 += __shfl_xor_sync(0xffffffffu, rs0, 2);
        rs1 += __shfl_xor_sync(0xffffffffu, rs1, 1);
        rs1 += __shfl_xor_sync(0xffffffffu, rs1, 2);
        l0r = l0r * corr0 + rs0;
        l1r = l1r * corr1 + rs1;
        #pragma unroll
        for (int nt = 0; nt < 8; nt++) {
            o[nt][0] *= corr0; o[nt][1] *= corr0;
            o[nt][2] *= corr1; o[nt][3] *= corr1;
        }

        __syncthreads();   // all warps done reading Ks -> overlay P
        {
            const int r0 = w * 16 + (lane >> 2);
            const int cc = (lane & 3) * 2;
            #pragma unroll
            for (int nt = 0; nt < 8; nt++) {
                *(float2*)(Ks + r0 * FROW + nt * 8 + cc) =
                    make_float2(tf32f(sf[nt][0]), tf32f(sf[nt][1]));
                *(float2*)(Ks + (r0 + 8) * FROW + nt * 8 + cc) =
                    make_float2(tf32f(sf[nt][2]), tf32f(sf[nt][3]));
            }
        }
        __syncwarp();   // warp reads back only its own P rows

        // O += P V  (A = P m16 x k64 from Ks region, B = Vt)
        #pragma unroll
        for (int ks = 0; ks < 8; ks++) {
            uint32_t ap[4], bv[8][2];
            LDSM_X4(ap[0], ap[1], ap[2], ap[3], Kb_s + arow + ach + ks * 32);
            #pragma unroll
            for (int p = 0; p < 4; p++)
                LDSM_X4(bv[2*p][0], bv[2*p][1], bv[2*p+1][0], bv[2*p+1][1],
                        Vb_s + brow[p] + bch + ks * 32);
            #pragma unroll
            for (int nt = 0; nt < 8; nt++)
                mma_tf32(o[nt], ap, bv[nt]);
        }
    }

    // Epilogue: normalize, round to tf32 (W_o GEMM consumes via cp.async)
    const float inv0 = 1.f / l0r, inv1 = 1.f / l1r;
    const int row0 = q0 + w * 16 + (lane >> 2);
    const int col  = h * DKH + (lane & 3) * 2;
    float* Ob = Op + (size_t)b * SEQ * D_MODEL;
    #pragma unroll
    for (int nt = 0; nt < 8; nt++) {
        *(float2*)(Ob + (size_t)row0 * D_MODEL + col + nt * 8) =
            make_float2(tf32f(o[nt][0] * inv0), tf32f(o[nt][1] * inv0));
        *(float2*)(Ob + (size_t)(row0 + 8) * D_MODEL + col + nt * 8) =
            make_float2(tf32f(o[nt][2] * inv1), tf32f(o[nt][3] * inv1));
    }
}

// ======================================================================
extern "C" void kernel_launch(void* const* d_in, const int* in_sizes, int n_in,
                              void* d_out, int out_size)
{
    (void)in_sizes; (void)n_in; (void)out_size;
    const float* Q_in = (const float*)d_in[0];
    const float* K_in = (const float*)d_in[1];
    const float* V_in = (const float*)d_in[2];
    const float* W_q  = (const float*)d_in[3];
    const float* W_k  = (const float*)d_in[4];
    const float* W_v  = (const float*)d_in[5];
    const float* W_o  = (const float*)d_in[6];
    float* out = (float*)d_out;

    float *Qp, *Kp, *Vp, *Ct, *rQ, *rK, *rV, *rWq, *rWk, *rWv, *rWo;
    cudaGetSymbolAddress((void**)&Qp, g_Qp);
    cudaGetSymbolAddress((void**)&Kp, g_Kp);
    cudaGetSymbolAddress((void**)&Vp, g_Vp);
    cudaGetSymbolAddress((void**)&Ct, g_Ct);
    cudaGetSymbolAddress((void**)&rQ, g_rQ);
    cudaGetSymbolAddress((void**)&rK, g_rK);
    cudaGetSymbolAddress((void**)&rV, g_rV);
    cudaGetSymbolAddress((void**)&rWq, g_rWq);
    cudaGetSymbolAddress((void**)&rWk, g_rWk);
    cudaGetSymbolAddress((void**)&rWv, g_rWv);
    cudaGetSymbolAddress((void**)&rWo, g_rWo);

    cudaFuncSetAttribute(gemm_tc, cudaFuncAttributeMaxDynamicSharedMemorySize, GEMM_SMEM);
    cudaFuncSetAttribute(flash_tc, cudaFuncAttributeMaxDynamicSharedMemorySize, FLASH_SMEM);

    const int nBig = MTOT * D_MODEL / 4, nW = D_MODEL * D_MODEL / 4;
    round_tf32_k<<<(nBig + 255) / 256, 256>>>(Q_in, rQ, nBig);
    round_tf32_k<<<(nBig + 255) / 256, 256>>>(K_in, rK, nBig);
    round_tf32_k<<<(nBig + 255) / 256, 256>>>(V_in, rV, nBig);
    round_tf32_k<<<(nW + 255) / 256, 256>>>(W_q, rWq, nW);
    round_tf32_k<<<(nW + 255) / 256, 256>>>(W_k, rWk, nW);
    round_tf32_k<<<(nW + 255) / 256, 256>>>(W_v, rWv, nW);
    round_tf32_k<<<(nW + 255) / 256, 256>>>(W_o, rWo, nW);

    dim3 gproj(D_MODEL / 128, MTOT / 128);   // (8, 64)
    gemm_tc<<<gproj, 256, GEMM_SMEM>>>(rQ, rWq, Qp, 1);
    gemm_tc<<<gproj, 256, GEMM_SMEM>>>(rK, rWk, Kp, 1);
    gemm_tc<<<gproj, 256, GEMM_SMEM>>>(rV, rWv, Vp, 1);

    flash_tc<<<dim3(SEQ / 64, NHEAD, BATCH), 128, FLASH_SMEM>>>(Qp, Kp, Vp, Ct);

    gemm_tc<<<gproj, 256, GEMM_SMEM>>>(Ct, rWo, out, 0);
}

// round 7
// speedup vs baseline: 3.9942x; 1.2979x over previous
#include <cuda_runtime.h>
#include <cstdint>

#define D_MODEL 1024
#define NHEAD   16
#define DKH     64
#define BATCH   4
#define SEQ     2048
#define MTOT    (BATCH*SEQ)   // 8192

// Scratch
__device__ float g_Qp[(size_t)MTOT * D_MODEL];
__device__ float g_Kp[(size_t)MTOT * D_MODEL];
__device__ float g_Vt[(size_t)MTOT * D_MODEL];   // V^T layout: [b][h][d][seq]
__device__ float g_Ct[(size_t)MTOT * D_MODEL];
// tf32-RN pre-rounded copies (cp.async path cannot convert)
__device__ float g_rQ[(size_t)MTOT * D_MODEL];
__device__ float g_rK[(size_t)MTOT * D_MODEL];
__device__ float g_rV[(size_t)MTOT * D_MODEL];
__device__ float g_rWq[(size_t)D_MODEL * D_MODEL];
__device__ float g_rWk[(size_t)D_MODEL * D_MODEL];
__device__ float g_rWv[(size_t)D_MODEL * D_MODEL];
__device__ float g_rWo[(size_t)D_MODEL * D_MODEL];

// ---------------- PTX helpers ----------------
__device__ __forceinline__ float tf32f(float x) {
    uint32_t u;
    asm("cvt.rn.tf32.f32 %0, %1;" : "=r"(u) : "f"(x));
    return __uint_as_float(u);
}
__device__ __forceinline__ float ex2f(float x) {
    float y;
    asm("ex2.approx.f32 %0, %1;" : "=f"(y) : "f"(x));
    return y;
}
__device__ __forceinline__ uint32_t smem_u32(const void* p) {
    uint32_t a;
    asm("{ .reg .u64 t; cvta.to.shared.u64 t, %1; cvt.u32.u64 %0, t; }" : "=r"(a) : "l"(p));
    return a;
}
__device__ __forceinline__ void mma_tf32(float c[4], const uint32_t a[4], const uint32_t b[2]) {
    asm volatile(
        "mma.sync.aligned.m16n8k8.row.col.f32.tf32.tf32.f32 "
        "{%0,%1,%2,%3}, {%4,%5,%6,%7}, {%8,%9}, {%0,%1,%2,%3};"
        : "+f"(c[0]), "+f"(c[1]), "+f"(c[2]), "+f"(c[3])
        : "r"(a[0]), "r"(a[1]), "r"(a[2]), "r"(a[3]), "r"(b[0]), "r"(b[1]));
}
#define LDSM_X4(r0,r1,r2,r3,addr) \
    asm volatile("ldmatrix.sync.aligned.m8n8.x4.shared.b16 {%0,%1,%2,%3}, [%4];" \
        : "=r"(r0),"=r"(r1),"=r"(r2),"=r"(r3) : "r"(addr))
#define CP16(sa, ga)  asm volatile("cp.async.cg.shared.global [%0], [%1], 16;" :: "r"(sa), "l"(ga))
#define CP_COMMIT()   asm volatile("cp.async.commit_group;" ::: "memory")
#define CP_WAIT(n)    asm volatile("cp.async.wait_group %0;" :: "n"(n) : "memory")

// ---------------- tf32-RN rounding pass ----------------
__global__ void round_tf32_k(const float* __restrict__ in, float* __restrict__ out, int n4)
{
    int i = blockIdx.x * blockDim.x + threadIdx.x;
    if (i < n4) {
        float4 v = ((const float4*)in)[i];
        v.x = tf32f(v.x); v.y = tf32f(v.y); v.z = tf32f(v.z); v.w = tf32f(v.w);
        ((float4*)out)[i] = v;
    }
}

// ======================================================================
// GEMM (NT): C[8192,1024] = A[8192,1024] * B[1024,1024]^T
// 128x128 CTA tile, BK=32, 3-stage cp.async, ldmatrix fragments.
// mode 0: raw fp32 C. mode 1: tf32-rounded C. mode 2: tf32-rounded,
// transposed-per-head V layout [b][h][d][seq].
// ======================================================================
#define GEMM_SMEM (3 * 32768)

__global__ __launch_bounds__(256, 2) void gemm_tc(
    const float* __restrict__ A, const float* __restrict__ B,
    float* __restrict__ C, int mode)
{
    extern __shared__ char sm[];
    const uint32_t sbase = smem_u32(sm);
    const int tid = threadIdx.x, lane = tid & 31, wid = tid >> 5;
    const int wm = (wid & 1) * 64, wn = (wid >> 1) * 32;
    const int m0 = blockIdx.y * 128, n0 = blockIdx.x * 128;

    float c[4][4][4];
    #pragma unroll
    for (int i = 0; i < 4; i++)
        #pragma unroll
        for (int j = 0; j < 4; j++)
            #pragma unroll
            for (int r = 0; r < 4; r++) c[i][j][r] = 0.f;

    auto issue = [&](int kt, int buf) {
        #pragma unroll
        for (int i = 0; i < 4; i++) {
            const int id = tid + 256 * i;
            const int row = id >> 3, cx = id & 7;
            const uint32_t off = row * 128 + (((uint32_t)(cx ^ (row & 7))) << 4);
            const float* ga = A + (size_t)(m0 + row) * 1024 + kt * 32 + cx * 4;
            const float* gb = B + (size_t)(n0 + row) * 1024 + kt * 32 + cx * 4;
            CP16(sbase + buf * 32768 + off, ga);
            CP16(sbase + buf * 32768 + 16384 + off, gb);
        }
        CP_COMMIT();
    };

    issue(0, 0);
    issue(1, 1);

    const int NKT = 32;
    for (int kt = 0; kt < NKT; kt++) {
        if (kt + 1 < NKT) { CP_WAIT(1); } else { CP_WAIT(0); }
        __syncthreads();
        if (kt + 2 < NKT) issue(kt + 2, (kt + 2) % 3);

        const uint32_t abase = sbase + (kt % 3) * 32768;
        const uint32_t bbase = abase + 16384;
        #pragma unroll
        for (int ks = 0; ks < 4; ks++) {
            uint32_t a[4][4], b[4][2];
            #pragma unroll
            for (int mt = 0; mt < 4; mt++) {
                const int row = wm + mt * 16 + (lane & 7) + ((lane >> 3) & 1) * 8;
                const int ch  = ks * 2 + (lane >> 4);
                const uint32_t ad = abase + row * 128 + (((uint32_t)(ch ^ (row & 7))) << 4);
                LDSM_X4(a[mt][0], a[mt][1], a[mt][2], a[mt][3], ad);
            }
            #pragma unroll
            for (int p = 0; p < 2; p++) {
                const int row = wn + p * 16 + (lane & 7) + (lane >> 4) * 8;
                const int ch  = ks * 2 + ((lane >> 3) & 1);
                const uint32_t bd = bbase + row * 128 + (((uint32_t)(ch ^ (row & 7))) << 4);
                LDSM_X4(b[2*p][0], b[2*p][1], b[2*p+1][0], b[2*p+1][1], bd);
            }
            #pragma unroll
            for (int mt = 0; mt < 4; mt++)
                #pragma unroll
                for (int nt = 0; nt < 4; nt++)
                    mma_tf32(c[mt][nt], a[mt], b[nt]);
        }
    }

    const int mbase = m0 + wm + (lane >> 2);
    const int nbase = n0 + wn + (lane & 3) * 2;
    if (mode == 2) {
        // transposed-per-head V^T layout [b][h][d][seq]
        #pragma unroll
        for (int mt = 0; mt < 4; mt++) {
            #pragma unroll
            for (int nt = 0; nt < 4; nt++) {
                #pragma unroll
                for (int r = 0; r < 4; r++) {
                    const int m = mbase + mt * 16 + (r >> 1) * 8;
                    const int n = nbase + nt * 8 + (r & 1);
                    const int bb = m >> 11, s = m & 2047;
                    const int hh = n >> 6, d = n & 63;
                    C[(((size_t)bb * 16 + hh) * 64 + d) * 2048 + s] = tf32f(c[mt][nt][r]);
                }
            }
        }
    } else {
        #pragma unroll
        for (int mt = 0; mt < 4; mt++) {
            #pragma unroll
            for (int nt = 0; nt < 4; nt++) {
                float v0 = c[mt][nt][0], v1 = c[mt][nt][1];
                float v2 = c[mt][nt][2], v3 = c[mt][nt][3];
                if (mode == 1) { v0 = tf32f(v0); v1 = tf32f(v1); v2 = tf32f(v2); v3 = tf32f(v3); }
                float* p0 = C + (size_t)(mbase + mt*16)     * 1024 + nbase + nt*8;
                float* p1 = C + (size_t)(mbase + mt*16 + 8) * 1024 + nbase + nt*8;
                *(float2*)p0 = make_float2(v0, v1);
                *(float2*)p1 = make_float2(v2, v3);
            }
        }
    }
}

// ======================================================================
// Flash attention v4: BQ=64, 4 warps (R4-proven geometry: P overlay is
// 64x64 and exactly fits K[buf]), cp.async double-buffered K / V^T,
// prefetch issued at END of iteration (buffer fully dead), softmax scale
// folded into ex2. Smem (floats): Qs 64x68 | K0 | K1 | V0 | V1 = 87040 B.
// ======================================================================
#define FROW  68
#define KS_F  (64 * FROW)
#define VS_F  (KS_F + 2 * 64 * FROW)
#define FLASH_SMEM ((VS_F + 2 * 64 * FROW) * 4)
#define SM_SCALE_LOG2E 0.1803368801111204f   // 0.125 * log2(e)

__global__ __launch_bounds__(128, 2) void flash_tc(
    const float* __restrict__ Qp, const float* __restrict__ Kp,
    const float* __restrict__ Vt, float* __restrict__ Op)
{
    extern __shared__ float fs[];
    const uint32_t sb = smem_u32(fs);
    const int tid = threadIdx.x, lane = tid & 31, w = tid >> 5;
    const int b = blockIdx.z, h = blockIdx.y;
    const int q0 = blockIdx.x * 64;

    const float* Qg = Qp + ((size_t)b * SEQ + q0) * D_MODEL + h * DKH;
    const float* Kg = Kp + (size_t)b * SEQ * D_MODEL + h * DKH;
    const float* Vg = Vt + ((size_t)(b * 16 + h) * 64) * 2048;

    auto issueKV = [&](int kt, int buf) {
        const uint32_t kb = sb + (KS_F + buf * 64 * FROW) * 4;
        const uint32_t vb = sb + (VS_F + buf * 64 * FROW) * 4;
        #pragma unroll
        for (int i = 0; i < 8; i++) {
            const int id = tid + 128 * i;
            const int row = id >> 4, cx = id & 15;
            CP16(kb + row * (FROW * 4) + cx * 16,
                 Kg + (size_t)(kt * 64 + row) * D_MODEL + cx * 4);
            CP16(vb + row * (FROW * 4) + cx * 16,
                 Vg + (size_t)row * 2048 + kt * 64 + cx * 4);
        }
        CP_COMMIT();
    };

    // prologue: Q + K0/V0 as one group, K1/V1 as a second group
    #pragma unroll
    for (int i = 0; i < 8; i++) {
        const int id = tid + 128 * i;
        const int row = id >> 4, cx = id & 15;
        CP16(sb + row * (FROW * 4) + cx * 16,
             Qg + (size_t)row * D_MODEL + cx * 4);
    }
    issueKV(0, 0);
    issueKV(1, 1);

    float o[8][4];
    #pragma unroll
    for (int nt = 0; nt < 8; nt++)
        #pragma unroll
        for (int j = 0; j < 4; j++) o[nt][j] = 0.f;
    float m0r = -1e30f, m1r = -1e30f, l0r = 0.f, l1r = 0.f;

    const uint32_t arow = (uint32_t)(w * 16 + (lane & 7) + ((lane >> 3) & 1) * 8) * (FROW * 4);
    const uint32_t ach  = (uint32_t)(lane >> 4) * 16;
    uint32_t brow[4];
    #pragma unroll
    for (int p = 0; p < 4; p++)
        brow[p] = (uint32_t)(p * 16 + (lane & 7) + (lane >> 4) * 8) * (FROW * 4);
    const uint32_t bch = (uint32_t)((lane >> 3) & 1) * 16;

    const int NKT = SEQ / 64;
    for (int kt = 0; kt < NKT; kt++) {
        if (kt + 1 < NKT) { CP_WAIT(1); } else { CP_WAIT(0); }
        __syncthreads();

        const int buf = kt & 1;
        const uint32_t Kb_s = sb + (KS_F + buf * 64 * FROW) * 4;
        const uint32_t Vb_s = sb + (VS_F + buf * 64 * FROW) * 4;

        // S = Q K^T  (raw scores; softmax scale folded into exp)
        float sf[8][4];
        #pragma unroll
        for (int nt = 0; nt < 8; nt++)
            #pragma unroll
            for (int j = 0; j < 4; j++) sf[nt][j] = 0.f;

        #pragma unroll
        for (int ks = 0; ks < 8; ks++) {
            uint32_t aq[4], bk[8][2];
            LDSM_X4(aq[0], aq[1], aq[2], aq[3], sb + arow + ach + ks * 32);
            #pragma unroll
            for (int p = 0; p < 4; p++)
                LDSM_X4(bk[2*p][0], bk[2*p][1], bk[2*p+1][0], bk[2*p+1][1],
                        Kb_s + brow[p] + bch + ks * 32);
            #pragma unroll
            for (int nt = 0; nt < 8; nt++)
                mma_tf32(sf[nt], aq, bk[nt]);
        }

        // Online softmax: p = 2^((s - m) * 0.125*log2e)
        float mn0 = m0r, mn1 = m1r;
        #pragma unroll
        for (int nt = 0; nt < 8; nt++) {
            mn0 = fmaxf(mn0, fmaxf(sf[nt][0], sf[nt][1]));
            mn1 = fmaxf(mn1, fmaxf(sf[nt][2], sf[nt][3]));
        }
        mn0 = fmaxf(mn0, __shfl_xor_sync(0xffffffffu, mn0, 1));
        mn0 = fmaxf(mn0, __shfl_xor_sync(0xffffffffu, mn0, 2));
        mn1 = fmaxf(mn1, __shfl_xor_sync(0xffffffffu, mn1, 1));
        mn1 = fmaxf(mn1, __shfl_xor_sync(0xffffffffu, mn1, 2));
        const float corr0 = ex2f((m0r - mn0) * SM_SCALE_LOG2E);
        const float corr1 = ex2f((m1r - mn1) * SM_SCALE_LOG2E);
        m0r = mn0; m1r = mn1;
        const float nc0 = -mn0 * SM_SCALE_LOG2E;
        const float nc1 = -mn1 * SM_SCALE_LOG2E;

        float rs0 = 0.f, rs1 = 0.f;
        #pragma unroll
        for (int nt = 0; nt < 8; nt++) {
            sf[nt][0] = ex2f(fmaf(sf[nt][0], SM_SCALE_LOG2E, nc0));
            sf[nt][1] = ex2f(fmaf(sf[nt][1], SM_SCALE_LOG2E, nc0));
            sf[nt][2] = ex2f(fmaf(sf[nt][2], SM_SCALE_LOG2E, nc1));
            sf[nt][3] = ex2f(fmaf(sf[nt][3], SM_SCALE_LOG2E, nc1));
            rs0 += sf[nt][0] + sf[nt][1];
            rs1 += sf[nt][2] + sf[nt][3];
        }
        rs0 += __shfl_xor_sync(0xffffffffu, rs0, 1);
        rs0 += __shfl_xor_sync(0xffffffffu, rs0, 2);
        rs1 += __shfl_xor_sync(0xffffffffu, rs1, 1);
        rs1 += __shfl_xor_sync(0xffffffffu, rs1, 2);
        l0r = l0r * corr0 + rs0;
        l1r = l1r * corr1 + rs1;
        #pragma unroll
        for (int nt = 0; nt < 8; nt++) {
            o[nt][0] *= corr0; o[nt][1] *= corr0;
            o[nt][2] *= corr1; o[nt][3] *= corr1;
        }

        __syncthreads();   // all warps done reading K[buf] -> overlay P (64 rows, fits)
        {
            float* Ks = fs + KS_F + buf * 64 * FROW;
            const int r0 = w * 16 + (lane >> 2);
            const int cc = (lane & 3) * 2;
            #pragma unroll
            for (int nt = 0; nt < 8; nt++) {
                *(float2*)(Ks + r0 * FROW + nt * 8 + cc) =
                    make_float2(tf32f(sf[nt][0]), tf32f(sf[nt][1]));
                *(float2*)(Ks + (r0 + 8) * FROW + nt * 8 + cc) =
                    make_float2(tf32f(sf[nt][2]), tf32f(sf[nt][3]));
            }
        }
        __syncwarp();   // each warp reads back only its own 16 P rows

        // O += P V
        #pragma unroll
        for (int ks = 0; ks < 8; ks++) {
            uint32_t ap[4], bv[8][2];
            LDSM_X4(ap[0], ap[1], ap[2], ap[3], Kb_s + arow + ach + ks * 32);
            #pragma unroll
            for (int p = 0; p < 4; p++)
                LDSM_X4(bv[2*p][0], bv[2*p][1], bv[2*p+1][0], bv[2*p+1][1],
                        Vb_s + brow[p] + bch + ks * 32);
            #pragma unroll
            for (int nt = 0; nt < 8; nt++)
                mma_tf32(o[nt], ap, bv[nt]);
        }

        // Prefetch tile kt+2 into buf (kt&1) — buffer fully consumed now.
        if (kt + 2 < NKT) {
            __syncthreads();
            issueKV(kt + 2, buf);
        }
    }

    const float inv0 = 1.f / l0r, inv1 = 1.f / l1r;
    const int row0 = q0 + w * 16 + (lane >> 2);
    const int col  = h * DKH + (lane & 3) * 2;
    float* Ob = Op + (size_t)b * SEQ * D_MODEL;
    #pragma unroll
    for (int nt = 0; nt < 8; nt++) {
        *(float2*)(Ob + (size_t)row0 * D_MODEL + col + nt * 8) =
            make_float2(tf32f(o[nt][0] * inv0), tf32f(o[nt][1] * inv0));
        *(float2*)(Ob + (size_t)(row0 + 8) * D_MODEL + col + nt * 8) =
            make_float2(tf32f(o[nt][2] * inv1), tf32f(o[nt][3] * inv1));
    }
}

// ======================================================================
extern "C" void kernel_launch(void* const* d_in, const int* in_sizes, int n_in,
                              void* d_out, int out_size)
{
    (void)in_sizes; (void)n_in; (void)out_size;
    const float* Q_in = (const float*)d_in[0];
    const float* K_in = (const float*)d_in[1];
    const float* V_in = (const float*)d_in[2];
    const float* W_q  = (const float*)d_in[3];
    const float* W_k  = (const float*)d_in[4];
    const float* W_v  = (const float*)d_in[5];
    const float* W_o  = (const float*)d_in[6];
    float* out = (float*)d_out;

    float *Qp, *Kp, *Vt, *Ct, *rQ, *rK, *rV, *rWq, *rWk, *rWv, *rWo;
    cudaGetSymbolAddress((void**)&Qp, g_Qp);
    cudaGetSymbolAddress((void**)&Kp, g_Kp);
    cudaGetSymbolAddress((void**)&Vt, g_Vt);
    cudaGetSymbolAddress((void**)&Ct, g_Ct);
    cudaGetSymbolAddress((void**)&rQ, g_rQ);
    cudaGetSymbolAddress((void**)&rK, g_rK);
    cudaGetSymbolAddress((void**)&rV, g_rV);
    cudaGetSymbolAddress((void**)&rWq, g_rWq);
    cudaGetSymbolAddress((void**)&rWk, g_rWk);
    cudaGetSymbolAddress((void**)&rWv, g_rWv);
    cudaGetSymbolAddress((void**)&rWo, g_rWo);

    cudaFuncSetAttribute(gemm_tc, cudaFuncAttributeMaxDynamicSharedMemorySize, GEMM_SMEM);
    cudaFuncSetAttribute(flash_tc, cudaFuncAttributeMaxDynamicSharedMemorySize, FLASH_SMEM);

    const int nBig = MTOT * D_MODEL / 4, nW = D_MODEL * D_MODEL / 4;
    round_tf32_k<<<(nBig + 255) / 256, 256>>>(Q_in, rQ, nBig);
    round_tf32_k<<<(nBig + 255) / 256, 256>>>(K_in, rK, nBig);
    round_tf32_k<<<(nBig + 255) / 256, 256>>>(V_in, rV, nBig);
    round_tf32_k<<<(nW + 255) / 256, 256>>>(W_q, rWq, nW);
    round_tf32_k<<<(nW + 255) / 256, 256>>>(W_k, rWk, nW);
    round_tf32_k<<<(nW + 255) / 256, 256>>>(W_v, rWv, nW);
    round_tf32_k<<<(nW + 255) / 256, 256>>>(W_o, rWo, nW);

    dim3 gproj(D_MODEL / 128, MTOT / 128);   // (8, 64)
    gemm_tc<<<gproj, 256, GEMM_SMEM>>>(rQ, rWq, Qp, 1);
    gemm_tc<<<gproj, 256, GEMM_SMEM>>>(rK, rWk, Kp, 1);
    gemm_tc<<<gproj, 256, GEMM_SMEM>>>(rV, rWv, Vt, 2);   // writes V^T layout

    flash_tc<<<dim3(SEQ / 64, NHEAD, BATCH), 128, FLASH_SMEM>>>(Qp, Kp, Vt, Ct);

    gemm_tc<<<gproj, 256, GEMM_SMEM>>>(Ct, rWo, out, 0);
}

// round 8
// speedup vs baseline: 4.0941x; 1.0250x over previous
#include <cuda_runtime.h>
#include <cstdint>

#define D_MODEL 1024
#define NHEAD   16
#define DKH     64
#define BATCH   4
#define SEQ     2048
#define MTOT    (BATCH*SEQ)   // 8192

// Scratch
__device__ float g_Qp[(size_t)MTOT * D_MODEL];
__device__ float g_Kp[(size_t)MTOT * D_MODEL];
__device__ float g_Vt[(size_t)MTOT * D_MODEL];   // V^T layout: [b][h][d][seq]
__device__ float g_Ct[(size_t)MTOT * D_MODEL];
// tf32-RN pre-rounded copies (cp.async path cannot convert)
__device__ float g_rQ[(size_t)MTOT * D_MODEL];
__device__ float g_rK[(size_t)MTOT * D_MODEL];
__device__ float g_rV[(size_t)MTOT * D_MODEL];
__device__ float g_rWq[(size_t)D_MODEL * D_MODEL];
__device__ float g_rWk[(size_t)D_MODEL * D_MODEL];
__device__ float g_rWv[(size_t)D_MODEL * D_MODEL];
__device__ float g_rWo[(size_t)D_MODEL * D_MODEL];

// ---------------- PTX helpers ----------------
__device__ __forceinline__ float tf32f(float x) {
    uint32_t u;
    asm("cvt.rn.tf32.f32 %0, %1;" : "=r"(u) : "f"(x));
    return __uint_as_float(u);
}
__device__ __forceinline__ float ex2f(float x) {
    float y;
    asm("ex2.approx.f32 %0, %1;" : "=f"(y) : "f"(x));
    return y;
}
__device__ __forceinline__ uint32_t smem_u32(const void* p) {
    uint32_t a;
    asm("{ .reg .u64 t; cvta.to.shared.u64 t, %1; cvt.u32.u64 %0, t; }" : "=r"(a) : "l"(p));
    return a;
}
__device__ __forceinline__ void mma_tf32(float c[4], const uint32_t a[4], const uint32_t b[2]) {
    asm volatile(
        "mma.sync.aligned.m16n8k8.row.col.f32.tf32.tf32.f32 "
        "{%0,%1,%2,%3}, {%4,%5,%6,%7}, {%8,%9}, {%0,%1,%2,%3};"
        : "+f"(c[0]), "+f"(c[1]), "+f"(c[2]), "+f"(c[3])
        : "r"(a[0]), "r"(a[1]), "r"(a[2]), "r"(a[3]), "r"(b[0]), "r"(b[1]));
}
#define LDSM_X4(r0,r1,r2,r3,addr) \
    asm volatile("ldmatrix.sync.aligned.m8n8.x4.shared.b16 {%0,%1,%2,%3}, [%4];" \
        : "=r"(r0),"=r"(r1),"=r"(r2),"=r"(r3) : "r"(addr))
#define CP16(sa, ga)  asm volatile("cp.async.cg.shared.global [%0], [%1], 16;" :: "r"(sa), "l"(ga))
#define CP_COMMIT()   asm volatile("cp.async.commit_group;" ::: "memory")
#define CP_WAIT(n)    asm volatile("cp.async.wait_group %0;" :: "n"(n) : "memory")

// ---------------- fused tf32-RN rounding pass (one launch) ----------------
#define NB4 (MTOT * D_MODEL / 4)       // 2097152 float4 per activation
#define NW4 (D_MODEL * D_MODEL / 4)    // 262144 float4 per weight
#define NTOT4 (3 * NB4 + 4 * NW4)      // 7340032

__global__ void round_all(
    const float* __restrict__ Qi, const float* __restrict__ Ki, const float* __restrict__ Vi,
    const float* __restrict__ Wq, const float* __restrict__ Wk,
    const float* __restrict__ Wv, const float* __restrict__ Wo,
    float* __restrict__ rQ, float* __restrict__ rK, float* __restrict__ rV,
    float* __restrict__ rWq, float* __restrict__ rWk, float* __restrict__ rWv,
    float* __restrict__ rWo)
{
    const int i = blockIdx.x * blockDim.x + threadIdx.x;
    if (i >= NTOT4) return;
    const float4* src;
    float4* dst;
    int off;
    if (i < 3 * NB4) {
        const int seg = i / NB4;
        off = i - seg * NB4;
        src = (const float4*)(seg == 0 ? Qi : seg == 1 ? Ki : Vi);
        dst = (float4*)(seg == 0 ? rQ : seg == 1 ? rK : rV);
    } else {
        const int j = i - 3 * NB4;
        const int seg = j / NW4;
        off = j - seg * NW4;
        src = (const float4*)(seg == 0 ? Wq : seg == 1 ? Wk : seg == 2 ? Wv : Wo);
        dst = (float4*)(seg == 0 ? rWq : seg == 1 ? rWk : seg == 2 ? rWv : rWo);
    }
    float4 v = src[off];
    v.x = tf32f(v.x); v.y = tf32f(v.y); v.z = tf32f(v.z); v.w = tf32f(v.w);
    dst[off] = v;
}

// ======================================================================
// GEMM (NT): C[8192,1024] = A[8192,1024] * B[1024,1024]^T
// 128x128 CTA tile, BK=32, 3-stage cp.async, ldmatrix fragments.
// mode 0: raw fp32 C. mode 1: tf32-rounded C. mode 2: tf32-rounded,
// transposed-per-head V layout [b][h][d][seq], smem-staged coalesced store.
// ======================================================================
#define GEMM_SMEM (3 * 32768)

__global__ __launch_bounds__(256, 2) void gemm_tc(
    const float* __restrict__ A, const float* __restrict__ B,
    float* __restrict__ C, int mode)
{
    extern __shared__ char sm[];
    const uint32_t sbase = smem_u32(sm);
    const int tid = threadIdx.x, lane = tid & 31, wid = tid >> 5;
    const int wm = (wid & 1) * 64, wn = (wid >> 1) * 32;
    const int m0 = blockIdx.y * 128, n0 = blockIdx.x * 128;

    float c[4][4][4];
    #pragma unroll
    for (int i = 0; i < 4; i++)
        #pragma unroll
        for (int j = 0; j < 4; j++)
            #pragma unroll
            for (int r = 0; r < 4; r++) c[i][j][r] = 0.f;

    auto issue = [&](int kt, int buf) {
        #pragma unroll
        for (int i = 0; i < 4; i++) {
            const int id = tid + 256 * i;
            const int row = id >> 3, cx = id & 7;
            const uint32_t off = row * 128 + (((uint32_t)(cx ^ (row & 7))) << 4);
            const float* ga = A + (size_t)(m0 + row) * 1024 + kt * 32 + cx * 4;
            const float* gb = B + (size_t)(n0 + row) * 1024 + kt * 32 + cx * 4;
            CP16(sbase + buf * 32768 + off, ga);
            CP16(sbase + buf * 32768 + 16384 + off, gb);
        }
        CP_COMMIT();
    };

    issue(0, 0);
    issue(1, 1);

    const int NKT = 32;
    for (int kt = 0; kt < NKT; kt++) {
        if (kt + 1 < NKT) { CP_WAIT(1); } else { CP_WAIT(0); }
        __syncthreads();
        if (kt + 2 < NKT) issue(kt + 2, (kt + 2) % 3);

        const uint32_t abase = sbase + (kt % 3) * 32768;
        const uint32_t bbase = abase + 16384;
        #pragma unroll
        for (int ks = 0; ks < 4; ks++) {
            uint32_t a[4][4], b[4][2];
            #pragma unroll
            for (int mt = 0; mt < 4; mt++) {
                const int row = wm + mt * 16 + (lane & 7) + ((lane >> 3) & 1) * 8;
                const int ch  = ks * 2 + (lane >> 4);
                const uint32_t ad = abase + row * 128 + (((uint32_t)(ch ^ (row & 7))) << 4);
                LDSM_X4(a[mt][0], a[mt][1], a[mt][2], a[mt][3], ad);
            }
            #pragma unroll
            for (int p = 0; p < 2; p++) {
                const int row = wn + p * 16 + (lane & 7) + (lane >> 4) * 8;
                const int ch  = ks * 2 + ((lane >> 3) & 1);
                const uint32_t bd = bbase + row * 128 + (((uint32_t)(ch ^ (row & 7))) << 4);
                LDSM_X4(b[2*p][0], b[2*p][1], b[2*p+1][0], b[2*p+1][1], bd);
            }
            #pragma unroll
            for (int mt = 0; mt < 4; mt++)
                #pragma unroll
                for (int nt = 0; nt < 4; nt++)
                    mma_tf32(c[mt][nt], a[mt], b[nt]);
        }
    }

    if (mode == 2) {
        // Stage [128 n][128 m] in smem (pad 132), then coalesced V^T stores.
        __syncthreads();                    // all warps done with pipeline smem
        float* st = (float*)sm;             // 128*132*4 = 67584 B <= 96 KB
        #pragma unroll
        for (int mt = 0; mt < 4; mt++)
            #pragma unroll
            for (int nt = 0; nt < 4; nt++)
                #pragma unroll
                for (int r = 0; r < 4; r++) {
                    const int ml = wm + (lane >> 2) + mt * 16 + (r >> 1) * 8;
                    const int nl = wn + (lane & 3) * 2 + nt * 8 + (r & 1);
                    st[nl * 132 + ml] = tf32f(c[mt][nt][r]);
                }
        __syncthreads();
        const int bb = m0 >> 11, s0 = m0 & 2047;
        #pragma unroll
        for (int it = 0; it < 16; it++) {
            const int idx = tid + it * 256;
            const int dl = idx >> 5, c4 = idx & 31;
            const int n = n0 + dl, hh = n >> 6, d = n & 63;
            float4 v = *(float4*)&st[dl * 132 + c4 * 4];
            *(float4*)(C + (((size_t)bb * 16 + hh) * 64 + d) * 2048 + s0 + c4 * 4) = v;
        }
    } else {
        const int mbase = m0 + wm + (lane >> 2);
        const int nbase = n0 + wn + (lane & 3) * 2;
        #pragma unroll
        for (int mt = 0; mt < 4; mt++) {
            #pragma unroll
            for (int nt = 0; nt < 4; nt++) {
                float v0 = c[mt][nt][0], v1 = c[mt][nt][1];
                float v2 = c[mt][nt][2], v3 = c[mt][nt][3];
                if (mode == 1) { v0 = tf32f(v0); v1 = tf32f(v1); v2 = tf32f(v2); v3 = tf32f(v3); }
                float* p0 = C + (size_t)(mbase + mt*16)     * 1024 + nbase + nt*8;
                float* p1 = C + (size_t)(mbase + mt*16 + 8) * 1024 + nbase + nt*8;
                *(float2*)p0 = make_float2(v0, v1);
                *(float2*)p1 = make_float2(v2, v3);
            }
        }
    }
}

// ======================================================================
// Flash attention v5: BQ=64, 4 warps. Q fragments hoisted to registers
// (loaded once via ldmatrix from the staging buffer), dedicated P buffer
// (reuses the Q staging area), cp.async double-buffered K / V^T with
// end-of-iteration prefetch. Softmax scale folded into ex2.
// Smem (floats): K0 | K1 | V0 | V1 | PQ  (each 64 x 68)  = 87040 B.
// ======================================================================
#define FROW  68
#define KS_F  0
#define VS_F  (2 * 64 * FROW)
#define PQ_F  (4 * 64 * FROW)
#define FLASH_SMEM (5 * 64 * FROW * 4)
#define SM_SCALE_LOG2E 0.1803368801111204f   // 0.125 * log2(e)

__global__ __launch_bounds__(128, 2) void flash_tc(
    const float* __restrict__ Qp, const float* __restrict__ Kp,
    const float* __restrict__ Vt, float* __restrict__ Op)
{
    extern __shared__ float fs[];
    const uint32_t sb = smem_u32(fs);
    const int tid = threadIdx.x, lane = tid & 31, w = tid >> 5;
    const int b = blockIdx.z, h = blockIdx.y;
    const int q0 = blockIdx.x * 64;

    const float* Qg = Qp + ((size_t)b * SEQ + q0) * D_MODEL + h * DKH;
    const float* Kg = Kp + (size_t)b * SEQ * D_MODEL + h * DKH;
    const float* Vg = Vt + ((size_t)(b * 16 + h) * 64) * 2048;

    auto issueKV = [&](int kt, int buf) {
        const uint32_t kb = sb + (KS_F + buf * 64 * FROW) * 4;
        const uint32_t vb = sb + (VS_F + buf * 64 * FROW) * 4;
        #pragma unroll
        for (int i = 0; i < 8; i++) {
            const int id = tid + 128 * i;
            const int row = id >> 4, cx = id & 15;
            CP16(kb + row * (FROW * 4) + cx * 16,
                 Kg + (size_t)(kt * 64 + row) * D_MODEL + cx * 4);
            CP16(vb + row * (FROW * 4) + cx * 16,
                 Vg + (size_t)row * 2048 + kt * 64 + cx * 4);
        }
        CP_COMMIT();
    };

    // prologue: Q (into PQ staging) + K0/V0 as one group, K1/V1 second
    #pragma unroll
    for (int i = 0; i < 8; i++) {
        const int id = tid + 128 * i;
        const int row = id >> 4, cx = id & 15;
        CP16(sb + PQ_F * 4 + row * (FROW * 4) + cx * 16,
             Qg + (size_t)row * D_MODEL + cx * 4);
    }
    issueKV(0, 0);
    issueKV(1, 1);

    float o[8][4];
    #pragma unroll
    for (int nt = 0; nt < 8; nt++)
        #pragma unroll
        for (int j = 0; j < 4; j++) o[nt][j] = 0.f;
    float m0r = -1e30f, m1r = -1e30f, l0r = 0.f, l1r = 0.f;
    uint32_t qf[8][4];   // hoisted Q fragments (loop-invariant)

    const uint32_t arow = (uint32_t)(w * 16 + (lane & 7) + ((lane >> 3) & 1) * 8) * (FROW * 4);
    const uint32_t ach  = (uint32_t)(lane >> 4) * 16;
    uint32_t brow[4];
    #pragma unroll
    for (int p = 0; p < 4; p++)
        brow[p] = (uint32_t)(p * 16 + (lane & 7) + (lane >> 4) * 8) * (FROW * 4);
    const uint32_t bch = (uint32_t)((lane >> 3) & 1) * 16;

    const int NKT = SEQ / 64;
    for (int kt = 0; kt < NKT; kt++) {
        if (kt + 1 < NKT) { CP_WAIT(1); } else { CP_WAIT(0); }
        __syncthreads();

        if (kt == 0) {   // Q fragments: load once from staging (before P overwrites it)
            #pragma unroll
            for (int ks = 0; ks < 8; ks++)
                LDSM_X4(qf[ks][0], qf[ks][1], qf[ks][2], qf[ks][3],
                        sb + PQ_F * 4 + arow + ach + ks * 32);
        }

        const int buf = kt & 1;
        const uint32_t Kb_s = sb + (KS_F + buf * 64 * FROW) * 4;
        const uint32_t Vb_s = sb + (VS_F + buf * 64 * FROW) * 4;

        // S = Q K^T  (raw scores; softmax scale folded into exp)
        float sf[8][4];
        #pragma unroll
        for (int nt = 0; nt < 8; nt++)
            #pragma unroll
            for (int j = 0; j < 4; j++) sf[nt][j] = 0.f;

        #pragma unroll
        for (int ks = 0; ks < 8; ks++) {
            uint32_t bk[8][2];
            #pragma unroll
            for (int p = 0; p < 4; p++)
                LDSM_X4(bk[2*p][0], bk[2*p][1], bk[2*p+1][0], bk[2*p+1][1],
                        Kb_s + brow[p] + bch + ks * 32);
            #pragma unroll
            for (int nt = 0; nt < 8; nt++)
                mma_tf32(sf[nt], qf[ks], bk[nt]);
        }

        // Online softmax: p = 2^((s - m) * 0.125*log2e)
        float mn0 = m0r, mn1 = m1r;
        #pragma unroll
        for (int nt = 0; nt < 8; nt++) {
            mn0 = fmaxf(mn0, fmaxf(sf[nt][0], sf[nt][1]));
            mn1 = fmaxf(mn1, fmaxf(sf[nt][2], sf[nt][3]));
        }
        mn0 = fmaxf(mn0, __shfl_xor_sync(0xffffffffu, mn0, 1));
        mn0 = fmaxf(mn0, __shfl_xor_sync(0xffffffffu, mn0, 2));
        mn1 = fmaxf(mn1, __shfl_xor_sync(0xffffffffu, mn1, 1));
        mn1 = fmaxf(mn1, __shfl_xor_sync(0xffffffffu, mn1, 2));
        const float corr0 = ex2f((m0r - mn0) * SM_SCALE_LOG2E);
        const float corr1 = ex2f((m1r - mn1) * SM_SCALE_LOG2E);
        m0r = mn0; m1r = mn1;
        const float nc0 = -mn0 * SM_SCALE_LOG2E;
        const float nc1 = -mn1 * SM_SCALE_LOG2E;

        float rs0 = 0.f, rs1 = 0.f;
        #pragma unroll
        for (int nt = 0; nt < 8; nt++) {
            sf[nt][0] = ex2f(fmaf(sf[nt][0], SM_SCALE_LOG2E, nc0));
            sf[nt][1] = ex2f(fmaf(sf[nt][1], SM_SCALE_LOG2E, nc0));
            sf[nt][2] = ex2f(fmaf(sf[nt][2], SM_SCALE_LOG2E, nc1));
            sf[nt][3] = ex2f(fmaf(sf[nt][3], SM_SCALE_LOG2E, nc1));
            rs0 += sf[nt][0] + sf[nt][1];
            rs1 += sf[nt][2] + sf[nt][3];
        }
        rs0 += __shfl_xor_sync(0xffffffffu, rs0, 1);
        rs0 += __shfl_xor_sync(0xffffffffu, rs0, 2);
        rs1 += __shfl_xor_sync(0xffffffffu, rs1, 1);
        rs1 += __shfl_xor_sync(0xffffffffu, rs1, 2);
        l0r = l0r * corr0 + rs0;
        l1r = l1r * corr1 + rs1;
        #pragma unroll
        for (int nt = 0; nt < 8; nt++) {
            o[nt][0] *= corr0; o[nt][1] *= corr0;
            o[nt][2] *= corr1; o[nt][3] *= corr1;
        }

        // P -> dedicated buffer (warp-private rows; no block sync needed)
        {
            float* Ps = fs + PQ_F;
            const int r0 = w * 16 + (lane >> 2);
            const int cc = (lane & 3) * 2;
            #pragma unroll
            for (int nt = 0; nt < 8; nt++) {
                *(float2*)(Ps + r0 * FROW + nt * 8 + cc) =
                    make_float2(tf32f(sf[nt][0]), tf32f(sf[nt][1]));
                *(float2*)(Ps + (r0 + 8) * FROW + nt * 8 + cc) =
                    make_float2(tf32f(sf[nt][2]), tf32f(sf[nt][3]));
            }
        }
        __syncwarp();   // each warp reads back only its own 16 P rows

        // O += P V
        #pragma unroll
        for (int ks = 0; ks < 8; ks++) {
            uint32_t ap[4], bv[8][2];
            LDSM_X4(ap[0], ap[1], ap[2], ap[3], sb + PQ_F * 4 + arow + ach + ks * 32);
            #pragma unroll
            for (int p = 0; p < 4; p++)
                LDSM_X4(bv[2*p][0], bv[2*p][1], bv[2*p+1][0], bv[2*p+1][1],
                        Vb_s + brow[p] + bch + ks * 32);
            #pragma unroll
            for (int nt = 0; nt < 8; nt++)
                mma_tf32(o[nt], ap, bv[nt]);
        }

        // Prefetch tile kt+2 into buf (kt&1) — K[buf]/V[buf] fully consumed.
        if (kt + 2 < NKT) {
            __syncthreads();
            issueKV(kt + 2, buf);
        }
    }

    const float inv0 = 1.f / l0r, inv1 = 1.f / l1r;
    const int row0 = q0 + w * 16 + (lane >> 2);
    const int col  = h * DKH + (lane & 3) * 2;
    float* Ob = Op + (size_t)b * SEQ * D_MODEL;
    #pragma unroll
    for (int nt = 0; nt < 8; nt++) {
        *(float2*)(Ob + (size_t)row0 * D_MODEL + col + nt * 8) =
            make_float2(tf32f(o[nt][0] * inv0), tf32f(o[nt][1] * inv0));
        *(float2*)(Ob + (size_t)(row0 + 8) * D_MODEL + col + nt * 8) =
            make_float2(tf32f(o[nt][2] * inv1), tf32f(o[nt][3] * inv1));
    }
}

// ======================================================================
extern "C" void kernel_launch(void* const* d_in, const int* in_sizes, int n_in,
                              void* d_out, int out_size)
{
    (void)in_sizes; (void)n_in; (void)out_size;
    const float* Q_in = (const float*)d_in[0];
    const float* K_in = (const float*)d_in[1];
    const float* V_in = (const float*)d_in[2];
    const float* W_q  = (const float*)d_in[3];
    const float* W_k  = (const float*)d_in[4];
    const float* W_v  = (const float*)d_in[5];
    const float* W_o  = (const float*)d_in[6];
    float* out = (float*)d_out;

    float *Qp, *Kp, *Vt, *Ct, *rQ, *rK, *rV, *rWq, *rWk, *rWv, *rWo;
    cudaGetSymbolAddress((void**)&Qp, g_Qp);
    cudaGetSymbolAddress((void**)&Kp, g_Kp);
    cudaGetSymbolAddress((void**)&Vt, g_Vt);
    cudaGetSymbolAddress((void**)&Ct, g_Ct);
    cudaGetSymbolAddress((void**)&rQ, g_rQ);
    cudaGetSymbolAddress((void**)&rK, g_rK);
    cudaGetSymbolAddress((void**)&rV, g_rV);
    cudaGetSymbolAddress((void**)&rWq, g_rWq);
    cudaGetSymbolAddress((void**)&rWk, g_rWk);
    cudaGetSymbolAddress((void**)&rWv, g_rWv);
    cudaGetSymbolAddress((void**)&rWo, g_rWo);

    cudaFuncSetAttribute(gemm_tc, cudaFuncAttributeMaxDynamicSharedMemorySize, GEMM_SMEM);
    cudaFuncSetAttribute(flash_tc, cudaFuncAttributeMaxDynamicSharedMemorySize, FLASH_SMEM);

    round_all<<<(NTOT4 + 255) / 256, 256>>>(Q_in, K_in, V_in, W_q, W_k, W_v, W_o,
                                            rQ, rK, rV, rWq, rWk, rWv, rWo);

    dim3 gproj(D_MODEL / 128, MTOT / 128);   // (8, 64)
    gemm_tc<<<gproj, 256, GEMM_SMEM>>>(rQ, rWq, Qp, 1);
    gemm_tc<<<gproj, 256, GEMM_SMEM>>>(rK, rWk, Kp, 1);
    gemm_tc<<<gproj, 256, GEMM_SMEM>>>(rV, rWv, Vt, 2);   // writes V^T layout

    flash_tc<<<dim3(SEQ / 64, NHEAD, BATCH), 128, FLASH_SMEM>>>(Qp, Kp, Vt, Ct);

    gemm_tc<<<gproj, 256, GEMM_SMEM>>>(Ct, rWo, out, 0);
}

// round 9
// speedup vs baseline: 4.1289x; 1.0085x over previous
#include <cuda_runtime.h>
#include <cstdint>

#define D_MODEL 1024
#define NHEAD   16
#define DKH     64
#define BATCH   4
#define SEQ     2048
#define MTOT    (BATCH*SEQ)   // 8192

// Scratch
__device__ float g_Qp[(size_t)MTOT * D_MODEL];
__device__ float g_Kp[(size_t)MTOT * D_MODEL];
__device__ float g_Vt[(size_t)MTOT * D_MODEL];   // V^T layout: [b][h][d][seq]
__device__ float g_Ct[(size_t)MTOT * D_MODEL];
// tf32-RN pre-rounded copies (cp.async path cannot convert)
__device__ float g_rQ[(size_t)MTOT * D_MODEL];
__device__ float g_rK[(size_t)MTOT * D_MODEL];
__device__ float g_rV[(size_t)MTOT * D_MODEL];
__device__ float g_rWq[(size_t)D_MODEL * D_MODEL];
__device__ float g_rWk[(size_t)D_MODEL * D_MODEL];
__device__ float g_rWv[(size_t)D_MODEL * D_MODEL];
__device__ float g_rWo[(size_t)D_MODEL * D_MODEL];

// ---------------- PTX helpers ----------------
__device__ __forceinline__ float tf32f(float x) {
    uint32_t u;
    asm("cvt.rn.tf32.f32 %0, %1;" : "=r"(u) : "f"(x));
    return __uint_as_float(u);
}
__device__ __forceinline__ float ex2f(float x) {
    float y;
    asm("ex2.approx.f32 %0, %1;" : "=f"(y) : "f"(x));
    return y;
}
__device__ __forceinline__ uint32_t smem_u32(const void* p) {
    uint32_t a;
    asm("{ .reg .u64 t; cvta.to.shared.u64 t, %1; cvt.u32.u64 %0, t; }" : "=r"(a) : "l"(p));
    return a;
}
__device__ __forceinline__ void mma_tf32(float c[4], const uint32_t a[4], const uint32_t b[2]) {
    asm volatile(
        "mma.sync.aligned.m16n8k8.row.col.f32.tf32.tf32.f32 "
        "{%0,%1,%2,%3}, {%4,%5,%6,%7}, {%8,%9}, {%0,%1,%2,%3};"
        : "+f"(c[0]), "+f"(c[1]), "+f"(c[2]), "+f"(c[3])
        : "r"(a[0]), "r"(a[1]), "r"(a[2]), "r"(a[3]), "r"(b[0]), "r"(b[1]));
}
#define LDSM_X4(r0,r1,r2,r3,addr) \
    asm volatile("ldmatrix.sync.aligned.m8n8.x4.shared.b16 {%0,%1,%2,%3}, [%4];" \
        : "=r"(r0),"=r"(r1),"=r"(r2),"=r"(r3) : "r"(addr))
#define CP16(sa, ga)  asm volatile("cp.async.cg.shared.global [%0], [%1], 16;" :: "r"(sa), "l"(ga))
#define CP_COMMIT()   asm volatile("cp.async.commit_group;" ::: "memory")
#define CP_WAIT(n)    asm volatile("cp.async.wait_group %0;" :: "n"(n) : "memory")

// ---------------- fused tf32-RN rounding pass (one launch) ----------------
#define NB4 (MTOT * D_MODEL / 4)
#define NW4 (D_MODEL * D_MODEL / 4)
#define NTOT4 (3 * NB4 + 4 * NW4)

__global__ void round_all(
    const float* __restrict__ Qi, const float* __restrict__ Ki, const float* __restrict__ Vi,
    const float* __restrict__ Wq, const float* __restrict__ Wk,
    const float* __restrict__ Wv, const float* __restrict__ Wo,
    float* __restrict__ rQ, float* __restrict__ rK, float* __restrict__ rV,
    float* __restrict__ rWq, float* __restrict__ rWk, float* __restrict__ rWv,
    float* __restrict__ rWo)
{
    const int i = blockIdx.x * blockDim.x + threadIdx.x;
    if (i >= NTOT4) return;
    const float4* src;
    float4* dst;
    int off;
    if (i < 3 * NB4) {
        const int seg = i / NB4;
        off = i - seg * NB4;
        src = (const float4*)(seg == 0 ? Qi : seg == 1 ? Ki : Vi);
        dst = (float4*)(seg == 0 ? rQ : seg == 1 ? rK : rV);
    } else {
        const int j = i - 3 * NB4;
        const int seg = j / NW4;
        off = j - seg * NW4;
        src = (const float4*)(seg == 0 ? Wq : seg == 1 ? Wk : seg == 2 ? Wv : Wo);
        dst = (float4*)(seg == 0 ? rWq : seg == 1 ? rWk : seg == 2 ? rWv : rWo);
    }
    float4 v = src[off];
    v.x = tf32f(v.x); v.y = tf32f(v.y); v.z = tf32f(v.z); v.w = tf32f(v.w);
    dst[off] = v;
}

// ======================================================================
// GEMM core (NT): C[8192,1024] = A * B^T. 128x128 tile, BK=32, 3-stage
// cp.async, ldmatrix. mode 0: raw fp32. mode 1: tf32-rounded.
// mode 2: tf32-rounded V^T layout [b][h][d][seq], smem-staged stores.
// ======================================================================
#define GEMM_SMEM (3 * 32768)

__device__ __forceinline__ void gemm_body(
    const float* __restrict__ A, const float* __restrict__ B,
    float* __restrict__ C, int mode, char* sm)
{
    const uint32_t sbase = smem_u32(sm);
    const int tid = threadIdx.x, lane = tid & 31, wid = tid >> 5;
    const int wm = (wid & 1) * 64, wn = (wid >> 1) * 32;
    const int m0 = blockIdx.y * 128, n0 = blockIdx.x * 128;

    float c[4][4][4];
    #pragma unroll
    for (int i = 0; i < 4; i++)
        #pragma unroll
        for (int j = 0; j < 4; j++)
            #pragma unroll
            for (int r = 0; r < 4; r++) c[i][j][r] = 0.f;

    auto issue = [&](int kt, int buf) {
        #pragma unroll
        for (int i = 0; i < 4; i++) {
            const int id = tid + 256 * i;
            const int row = id >> 3, cx = id & 7;
            const uint32_t off = row * 128 + (((uint32_t)(cx ^ (row & 7))) << 4);
            const float* ga = A + (size_t)(m0 + row) * 1024 + kt * 32 + cx * 4;
            const float* gb = B + (size_t)(n0 + row) * 1024 + kt * 32 + cx * 4;
            CP16(sbase + buf * 32768 + off, ga);
            CP16(sbase + buf * 32768 + 16384 + off, gb);
        }
        CP_COMMIT();
    };

    issue(0, 0);
    issue(1, 1);

    const int NKT = 32;
    for (int kt = 0; kt < NKT; kt++) {
        if (kt + 1 < NKT) { CP_WAIT(1); } else { CP_WAIT(0); }
        __syncthreads();
        if (kt + 2 < NKT) issue(kt + 2, (kt + 2) % 3);

        const uint32_t abase = sbase + (kt % 3) * 32768;
        const uint32_t bbase = abase + 16384;
        #pragma unroll
        for (int ks = 0; ks < 4; ks++) {
            uint32_t a[4][4], b[4][2];
            #pragma unroll
            for (int mt = 0; mt < 4; mt++) {
                const int row = wm + mt * 16 + (lane & 7) + ((lane >> 3) & 1) * 8;
                const int ch  = ks * 2 + (lane >> 4);
                const uint32_t ad = abase + row * 128 + (((uint32_t)(ch ^ (row & 7))) << 4);
                LDSM_X4(a[mt][0], a[mt][1], a[mt][2], a[mt][3], ad);
            }
            #pragma unroll
            for (int p = 0; p < 2; p++) {
                const int row = wn + p * 16 + (lane & 7) + (lane >> 4) * 8;
                const int ch  = ks * 2 + ((lane >> 3) & 1);
                const uint32_t bd = bbase + row * 128 + (((uint32_t)(ch ^ (row & 7))) << 4);
                LDSM_X4(b[2*p][0], b[2*p][1], b[2*p+1][0], b[2*p+1][1], bd);
            }
            #pragma unroll
            for (int mt = 0; mt < 4; mt++)
                #pragma unroll
                for (int nt = 0; nt < 4; nt++)
                    mma_tf32(c[mt][nt], a[mt], b[nt]);
        }
    }

    if (mode == 2) {
        __syncthreads();
        float* st = (float*)sm;             // 128*132*4 = 67584 B
        #pragma unroll
        for (int mt = 0; mt < 4; mt++)
            #pragma unroll
            for (int nt = 0; nt < 4; nt++)
                #pragma unroll
                for (int r = 0; r < 4; r++) {
                    const int ml = wm + (lane >> 2) + mt * 16 + (r >> 1) * 8;
                    const int nl = wn + (lane & 3) * 2 + nt * 8 + (r & 1);
                    st[nl * 132 + ml] = tf32f(c[mt][nt][r]);
                }
        __syncthreads();
        const int bb = m0 >> 11, s0 = m0 & 2047;
        #pragma unroll
        for (int it = 0; it < 16; it++) {
            const int idx = tid + it * 256;
            const int dl = idx >> 5, c4 = idx & 31;
            const int n = n0 + dl, hh = n >> 6, d = n & 63;
            float4 v = *(float4*)&st[dl * 132 + c4 * 4];
            *(float4*)(C + (((size_t)bb * 16 + hh) * 64 + d) * 2048 + s0 + c4 * 4) = v;
        }
    } else {
        const int mbase = m0 + wm + (lane >> 2);
        const int nbase = n0 + wn + (lane & 3) * 2;
        #pragma unroll
        for (int mt = 0; mt < 4; mt++) {
            #pragma unroll
            for (int nt = 0; nt < 4; nt++) {
                float v0 = c[mt][nt][0], v1 = c[mt][nt][1];
                float v2 = c[mt][nt][2], v3 = c[mt][nt][3];
                if (mode == 1) { v0 = tf32f(v0); v1 = tf32f(v1); v2 = tf32f(v2); v3 = tf32f(v3); }
                float* p0 = C + (size_t)(mbase + mt*16)     * 1024 + nbase + nt*8;
                float* p1 = C + (size_t)(mbase + mt*16 + 8) * 1024 + nbase + nt*8;
                *(float2*)p0 = make_float2(v0, v1);
                *(float2*)p1 = make_float2(v2, v3);
            }
        }
    }
}

// Fused QKV projections: blockIdx.z selects (A, B, C, mode).
__global__ __launch_bounds__(256, 2) void gemm_qkv(
    const float* __restrict__ A0, const float* __restrict__ A1, const float* __restrict__ A2,
    const float* __restrict__ B0, const float* __restrict__ B1, const float* __restrict__ B2,
    float* __restrict__ C0, float* __restrict__ C1, float* __restrict__ C2)
{
    extern __shared__ char sm[];
    const int z = blockIdx.z;
    const float* A = z == 0 ? A0 : z == 1 ? A1 : A2;
    const float* B = z == 0 ? B0 : z == 1 ? B1 : B2;
    float* C       = z == 0 ? C0 : z == 1 ? C1 : C2;
    gemm_body(A, B, C, z == 2 ? 2 : 1, sm);
}

__global__ __launch_bounds__(256, 2) void gemm_tc(
    const float* __restrict__ A, const float* __restrict__ B,
    float* __restrict__ C, int mode)
{
    extern __shared__ char sm[];
    gemm_body(A, B, C, mode, sm);
}

// ======================================================================
// Flash attention v6: BQ=128, 8 warps, dedicated 128-row P/Q region,
// 64-row double-buffered K / V^T via cp.async (end-of-iter prefetch).
// Halves K/V L2 traffic and per-work sync vs BQ=64.
// Smem (floats): K0|K1|V0|V1 (64x68 each) | PQ (128x68) = 104448 B.
// ======================================================================
#define FROW  68
#define KS_F  0
#define VS_F  (2 * 64 * FROW)
#define PQ_F  (4 * 64 * FROW)
#define FLASH_SMEM ((PQ_F + 128 * FROW) * 4)
#define SM_SCALE_LOG2E 0.1803368801111204f   // 0.125 * log2(e)

__global__ __launch_bounds__(256, 1) void flash_tc(
    const float* __restrict__ Qp, const float* __restrict__ Kp,
    const float* __restrict__ Vt, float* __restrict__ Op)
{
    extern __shared__ float fs[];
    const uint32_t sb = smem_u32(fs);
    const int tid = threadIdx.x, lane = tid & 31, w = tid >> 5;
    const int b = blockIdx.z, h = blockIdx.y;
    const int q0 = blockIdx.x * 128;

    const float* Qg = Qp + ((size_t)b * SEQ + q0) * D_MODEL + h * DKH;
    const float* Kg = Kp + (size_t)b * SEQ * D_MODEL + h * DKH;
    const float* Vg = Vt + ((size_t)(b * 16 + h) * 64) * 2048;

    auto issueKV = [&](int kt, int buf) {
        const uint32_t kb = sb + (KS_F + buf * 64 * FROW) * 4;
        const uint32_t vb = sb + (VS_F + buf * 64 * FROW) * 4;
        #pragma unroll
        for (int i = 0; i < 4; i++) {
            const int id = tid + 256 * i;
            const int row = id >> 4, cx = id & 15;
            CP16(kb + row * (FROW * 4) + cx * 16,
                 Kg + (size_t)(kt * 64 + row) * D_MODEL + cx * 4);
            CP16(vb + row * (FROW * 4) + cx * 16,
                 Vg + (size_t)row * 2048 + kt * 64 + cx * 4);
        }
        CP_COMMIT();
    };

    // prologue: Q (128 rows into PQ) + K0/V0 as one group, K1/V1 second
    #pragma unroll
    for (int i = 0; i < 8; i++) {
        const int id = tid + 256 * i;
        const int row = id >> 4, cx = id & 15;
        CP16(sb + PQ_F * 4 + row * (FROW * 4) + cx * 16,
             Qg + (size_t)row * D_MODEL + cx * 4);
    }
    issueKV(0, 0);
    issueKV(1, 1);

    float o[8][4];
    #pragma unroll
    for (int nt = 0; nt < 8; nt++)
        #pragma unroll
        for (int j = 0; j < 4; j++) o[nt][j] = 0.f;
    float m0r = -1e30f, m1r = -1e30f, l0r = 0.f, l1r = 0.f;
    uint32_t qf[8][4];   // hoisted Q fragments

    const uint32_t arow = (uint32_t)(w * 16 + (lane & 7) + ((lane >> 3) & 1) * 8) * (FROW * 4);
    const uint32_t ach  = (uint32_t)(lane >> 4) * 16;
    uint32_t brow[4];
    #pragma unroll
    for (int p = 0; p < 4; p++)
        brow[p] = (uint32_t)(p * 16 + (lane & 7) + (lane >> 4) * 8) * (FROW * 4);
    const uint32_t bch = (uint32_t)((lane >> 3) & 1) * 16;

    const int NKT = SEQ / 64;
    for (int kt = 0; kt < NKT; kt++) {
        if (kt + 1 < NKT) { CP_WAIT(1); } else { CP_WAIT(0); }
        __syncthreads();

        if (kt == 0) {   // Q fragments: once, before P overwrites the region
            #pragma unroll
            for (int ks = 0; ks < 8; ks++)
                LDSM_X4(qf[ks][0], qf[ks][1], qf[ks][2], qf[ks][3],
                        sb + PQ_F * 4 + arow + ach + ks * 32);
        }

        const int buf = kt & 1;
        const uint32_t Kb_s = sb + (KS_F + buf * 64 * FROW) * 4;
        const uint32_t Vb_s = sb + (VS_F + buf * 64 * FROW) * 4;

        // S = Q K^T
        float sf[8][4];
        #pragma unroll
        for (int nt = 0; nt < 8; nt++)
            #pragma unroll
            for (int j = 0; j < 4; j++) sf[nt][j] = 0.f;

        #pragma unroll
        for (int ks = 0; ks < 8; ks++) {
            uint32_t bk[8][2];
            #pragma unroll
            for (int p = 0; p < 4; p++)
                LDSM_X4(bk[2*p][0], bk[2*p][1], bk[2*p+1][0], bk[2*p+1][1],
                        Kb_s + brow[p] + bch + ks * 32);
            #pragma unroll
            for (int nt = 0; nt < 8; nt++)
                mma_tf32(sf[nt], qf[ks], bk[nt]);
        }

        // Online softmax: p = 2^((s - m) * 0.125*log2e)
        float mn0 = m0r, mn1 = m1r;
        #pragma unroll
        for (int nt = 0; nt < 8; nt++) {
            mn0 = fmaxf(mn0, fmaxf(sf[nt][0], sf[nt][1]));
            mn1 = fmaxf(mn1, fmaxf(sf[nt][2], sf[nt][3]));
        }
        mn0 = fmaxf(mn0, __shfl_xor_sync(0xffffffffu, mn0, 1));
        mn0 = fmaxf(mn0, __shfl_xor_sync(0xffffffffu, mn0, 2));
        mn1 = fmaxf(mn1, __shfl_xor_sync(0xffffffffu, mn1, 1));
        mn1 = fmaxf(mn1, __shfl_xor_sync(0xffffffffu, mn1, 2));
        const float corr0 = ex2f((m0r - mn0) * SM_SCALE_LOG2E);
        const float corr1 = ex2f((m1r - mn1) * SM_SCALE_LOG2E);
        m0r = mn0; m1r = mn1;
        const float nc0 = -mn0 * SM_SCALE_LOG2E;
        const float nc1 = -mn1 * SM_SCALE_LOG2E;

        float rs0 = 0.f, rs1 = 0.f;
        #pragma unroll
        for (int nt = 0; nt < 8; nt++) {
            sf[nt][0] = ex2f(fmaf(sf[nt][0], SM_SCALE_LOG2E, nc0));
            sf[nt][1] = ex2f(fmaf(sf[nt][1], SM_SCALE_LOG2E, nc0));
            sf[nt][2] = ex2f(fmaf(sf[nt][2], SM_SCALE_LOG2E, nc1));
            sf[nt][3] = ex2f(fmaf(sf[nt][3], SM_SCALE_LOG2E, nc1));
            rs0 += sf[nt][0] + sf[nt][1];
            rs1 += sf[nt][2] + sf[nt][3];
        }
        rs0 += __shfl_xor_sync(0xffffffffu, rs0, 1);
        rs0 += __shfl_xor_sync(0xffffffffu, rs0, 2);
        rs1 += __shfl_xor_sync(0xffffffffu, rs1, 1);
        rs1 += __shfl_xor_sync(0xffffffffu, rs1, 2);
        l0r = l0r * corr0 + rs0;
        l1r = l1r * corr1 + rs1;
        #pragma unroll
        for (int nt = 0; nt < 8; nt++) {
            o[nt][0] *= corr0; o[nt][1] *= corr0;
            o[nt][2] *= corr1; o[nt][3] *= corr1;
        }

        // P -> dedicated region (warp-private rows; 128 rows available)
        {
            float* Ps = fs + PQ_F;
            const int r0 = w * 16 + (lane >> 2);
            const int cc = (lane & 3) * 2;
            #pragma unroll
            for (int nt = 0; nt < 8; nt++) {
                *(float2*)(Ps + r0 * FROW + nt * 8 + cc) =
                    make_float2(tf32f(sf[nt][0]), tf32f(sf[nt][1]));
                *(float2*)(Ps + (r0 + 8) * FROW + nt * 8 + cc) =
                    make_float2(tf32f(sf[nt][2]), tf32f(sf[nt][3]));
            }
        }
        __syncwarp();   // each warp reads back only its own 16 P rows

        // O += P V
        #pragma unroll
        for (int ks = 0; ks < 8; ks++) {
            uint32_t ap[4], bv[8][2];
            LDSM_X4(ap[0], ap[1], ap[2], ap[3], sb + PQ_F * 4 + arow + ach + ks * 32);
            #pragma unroll
            for (int p = 0; p < 4; p++)
                LDSM_X4(bv[2*p][0], bv[2*p][1], bv[2*p+1][0], bv[2*p+1][1],
                        Vb_s + brow[p] + bch + ks * 32);
            #pragma unroll
            for (int nt = 0; nt < 8; nt++)
                mma_tf32(o[nt], ap, bv[nt]);
        }

        // Prefetch tile kt+2 into buf (kt&1) — K/V[buf] fully consumed.
        if (kt + 2 < NKT) {
            __syncthreads();
            issueKV(kt + 2, buf);
        }
    }

    const float inv0 = 1.f / l0r, inv1 = 1.f / l1r;
    const int row0 = q0 + w * 16 + (lane >> 2);
    const int col  = h * DKH + (lane & 3) * 2;
    float* Ob = Op + (size_t)b * SEQ * D_MODEL;
    #pragma unroll
    for (int nt = 0; nt < 8; nt++) {
        *(float2*)(Ob + (size_t)row0 * D_MODEL + col + nt * 8) =
            make_float2(tf32f(o[nt][0] * inv0), tf32f(o[nt][1] * inv0));
        *(float2*)(Ob + (size_t)(row0 + 8) * D_MODEL + col + nt * 8) =
            make_float2(tf32f(o[nt][2] * inv1), tf32f(o[nt][3] * inv1));
    }
}

// ======================================================================
extern "C" void kernel_launch(void* const* d_in, const int* in_sizes, int n_in,
                              void* d_out, int out_size)
{
    (void)in_sizes; (void)n_in; (void)out_size;
    const float* Q_in = (const float*)d_in[0];
    const float* K_in = (const float*)d_in[1];
    const float* V_in = (const float*)d_in[2];
    const float* W_q  = (const float*)d_in[3];
    const float* W_k  = (const float*)d_in[4];
    const float* W_v  = (const float*)d_in[5];
    const float* W_o  = (const float*)d_in[6];
    float* out = (float*)d_out;

    float *Qp, *Kp, *Vt, *Ct, *rQ, *rK, *rV, *rWq, *rWk, *rWv, *rWo;
    cudaGetSymbolAddress((void**)&Qp, g_Qp);
    cudaGetSymbolAddress((void**)&Kp, g_Kp);
    cudaGetSymbolAddress((void**)&Vt, g_Vt);
    cudaGetSymbolAddress((void**)&Ct, g_Ct);
    cudaGetSymbolAddress((void**)&rQ, g_rQ);
    cudaGetSymbolAddress((void**)&rK, g_rK);
    cudaGetSymbolAddress((void**)&rV, g_rV);
    cudaGetSymbolAddress((void**)&rWq, g_rWq);
    cudaGetSymbolAddress((void**)&rWk, g_rWk);
    cudaGetSymbolAddress((void**)&rWv, g_rWv);
    cudaGetSymbolAddress((void**)&rWo, g_rWo);

    cudaFuncSetAttribute(gemm_qkv, cudaFuncAttributeMaxDynamicSharedMemorySize, GEMM_SMEM);
    cudaFuncSetAttribute(gemm_tc, cudaFuncAttributeMaxDynamicSharedMemorySize, GEMM_SMEM);
    cudaFuncSetAttribute(flash_tc, cudaFuncAttributeMaxDynamicSharedMemorySize, FLASH_SMEM);

    round_all<<<(NTOT4 + 255) / 256, 256>>>(Q_in, K_in, V_in, W_q, W_k, W_v, W_o,
                                            rQ, rK, rV, rWq, rWk, rWv, rWo);

    // Fused Q/K/V projections: grid.z = 0/1/2 selects the GEMM.
    gemm_qkv<<<dim3(8, 64, 3), 256, GEMM_SMEM>>>(rQ, rK, rV, rWq, rWk, rWv, Qp, Kp, Vt);

    flash_tc<<<dim3(SEQ / 128, NHEAD, BATCH), 256, FLASH_SMEM>>>(Qp, Kp, Vt, Ct);

    gemm_tc<<<dim3(8, 64), 256, GEMM_SMEM>>>(Ct, rWo, out, 0);
}

// round 10
// speedup vs baseline: 5.9678x; 1.4454x over previous
#include <cuda_runtime.h>
#include <cuda_fp16.h>
#include <cstdint>

#define D_MODEL 1024
#define NHEAD   16
#define DKH     64
#define BATCH   4
#define SEQ     2048
#define MTOT    (BATCH*SEQ)   // 8192

// Scratch: projected Q/K/V in fp16 (natural [b][s][h*d] layout), Ct fp32.
__device__ __half g_Qp[(size_t)MTOT * D_MODEL];
__device__ __half g_Kp[(size_t)MTOT * D_MODEL];
__device__ __half g_Vp[(size_t)MTOT * D_MODEL];
__device__ float  g_Ct[(size_t)MTOT * D_MODEL];
// tf32-RN pre-rounded copies (cp.async path cannot convert)
__device__ float g_rQ[(size_t)MTOT * D_MODEL];
__device__ float g_rK[(size_t)MTOT * D_MODEL];
__device__ float g_rV[(size_t)MTOT * D_MODEL];
__device__ float g_rWq[(size_t)D_MODEL * D_MODEL];
__device__ float g_rWk[(size_t)D_MODEL * D_MODEL];
__device__ float g_rWv[(size_t)D_MODEL * D_MODEL];
__device__ float g_rWo[(size_t)D_MODEL * D_MODEL];

// ---------------- PTX helpers ----------------
__device__ __forceinline__ float tf32f(float x) {
    uint32_t u;
    asm("cvt.rn.tf32.f32 %0, %1;" : "=r"(u) : "f"(x));
    return __uint_as_float(u);
}
__device__ __forceinline__ float ex2f(float x) {
    float y;
    asm("ex2.approx.f32 %0, %1;" : "=f"(y) : "f"(x));
    return y;
}
__device__ __forceinline__ uint32_t smem_u32(const void* p) {
    uint32_t a;
    asm("{ .reg .u64 t; cvta.to.shared.u64 t, %1; cvt.u32.u64 %0, t; }" : "=r"(a) : "l"(p));
    return a;
}
__device__ __forceinline__ void mma_tf32(float c[4], const uint32_t a[4], const uint32_t b[2]) {
    asm volatile(
        "mma.sync.aligned.m16n8k8.row.col.f32.tf32.tf32.f32 "
        "{%0,%1,%2,%3}, {%4,%5,%6,%7}, {%8,%9}, {%0,%1,%2,%3};"
        : "+f"(c[0]), "+f"(c[1]), "+f"(c[2]), "+f"(c[3])
        : "r"(a[0]), "r"(a[1]), "r"(a[2]), "r"(a[3]), "r"(b[0]), "r"(b[1]));
}
__device__ __forceinline__ void mma_f16(float c[4], const uint32_t a[4],
                                        uint32_t b0, uint32_t b1) {
    asm volatile(
        "mma.sync.aligned.m16n8k16.row.col.f32.f16.f16.f32 "
        "{%0,%1,%2,%3}, {%4,%5,%6,%7}, {%8,%9}, {%0,%1,%2,%3};"
        : "+f"(c[0]), "+f"(c[1]), "+f"(c[2]), "+f"(c[3])
        : "r"(a[0]), "r"(a[1]), "r"(a[2]), "r"(a[3]), "r"(b0), "r"(b1));
}
#define LDSM_X4(r0,r1,r2,r3,addr) \
    asm volatile("ldmatrix.sync.aligned.m8n8.x4.shared.b16 {%0,%1,%2,%3}, [%4];" \
        : "=r"(r0),"=r"(r1),"=r"(r2),"=r"(r3) : "r"(addr))
#define LDSM_X4_T(r0,r1,r2,r3,addr) \
    asm volatile("ldmatrix.sync.aligned.m8n8.x4.trans.shared.b16 {%0,%1,%2,%3}, [%4];" \
        : "=r"(r0),"=r"(r1),"=r"(r2),"=r"(r3) : "r"(addr))
#define CP16(sa, ga)  asm volatile("cp.async.cg.shared.global [%0], [%1], 16;" :: "r"(sa), "l"(ga))
#define CP_COMMIT()   asm volatile("cp.async.commit_group;" ::: "memory")
#define CP_WAIT(n)    asm volatile("cp.async.wait_group %0;" :: "n"(n) : "memory")

// ---------------- fused tf32-RN rounding pass ----------------
#define NB4 (MTOT * D_MODEL / 4)
#define NW4 (D_MODEL * D_MODEL / 4)
#define NTOT4 (3 * NB4 + 4 * NW4)

__global__ void round_all(
    const float* __restrict__ Qi, const float* __restrict__ Ki, const float* __restrict__ Vi,
    const float* __restrict__ Wq, const float* __restrict__ Wk,
    const float* __restrict__ Wv, const float* __restrict__ Wo,
    float* __restrict__ rQ, float* __restrict__ rK, float* __restrict__ rV,
    float* __restrict__ rWq, float* __restrict__ rWk, float* __restrict__ rWv,
    float* __restrict__ rWo)
{
    const int i = blockIdx.x * blockDim.x + threadIdx.x;
    if (i >= NTOT4) return;
    const float4* src;
    float4* dst;
    int off;
    if (i < 3 * NB4) {
        const int seg = i / NB4;
        off = i - seg * NB4;
        src = (const float4*)(seg == 0 ? Qi : seg == 1 ? Ki : Vi);
        dst = (float4*)(seg == 0 ? rQ : seg == 1 ? rK : rV);
    } else {
        const int j = i - 3 * NB4;
        const int seg = j / NW4;
        off = j - seg * NW4;
        src = (const float4*)(seg == 0 ? Wq : seg == 1 ? Wk : seg == 2 ? Wv : Wo);
        dst = (float4*)(seg == 0 ? rWq : seg == 1 ? rWk : seg == 2 ? rWv : rWo);
    }
    float4 v = src[off];
    v.x = tf32f(v.x); v.y = tf32f(v.y); v.z = tf32f(v.z); v.w = tf32f(v.w);
    dst[off] = v;
}

// ======================================================================
// GEMM core (NT): C[8192,1024] = A * B^T. 128x128 tile, BK=32, 3-stage
// cp.async, ldmatrix. mode 0: raw fp32 out. mode 1: fp16 out.
// ======================================================================
#define GEMM_SMEM (3 * 32768)

__device__ __forceinline__ void gemm_body(
    const float* __restrict__ A, const float* __restrict__ B,
    void* __restrict__ Cv, int mode, char* sm)
{
    const uint32_t sbase = smem_u32(sm);
    const int tid = threadIdx.x, lane = tid & 31, wid = tid >> 5;
    const int wm = (wid & 1) * 64, wn = (wid >> 1) * 32;
    const int m0 = blockIdx.y * 128, n0 = blockIdx.x * 128;

    float c[4][4][4];
    #pragma unroll
    for (int i = 0; i < 4; i++)
        #pragma unroll
        for (int j = 0; j < 4; j++)
            #pragma unroll
            for (int r = 0; r < 4; r++) c[i][j][r] = 0.f;

    auto issue = [&](int kt, int buf) {
        #pragma unroll
        for (int i = 0; i < 4; i++) {
            const int id = tid + 256 * i;
            const int row = id >> 3, cx = id & 7;
            const uint32_t off = row * 128 + (((uint32_t)(cx ^ (row & 7))) << 4);
            const float* ga = A + (size_t)(m0 + row) * 1024 + kt * 32 + cx * 4;
            const float* gb = B + (size_t)(n0 + row) * 1024 + kt * 32 + cx * 4;
            CP16(sbase + buf * 32768 + off, ga);
            CP16(sbase + buf * 32768 + 16384 + off, gb);
        }
        CP_COMMIT();
    };

    issue(0, 0);
    issue(1, 1);

    const int NKT = 32;
    for (int kt = 0; kt < NKT; kt++) {
        if (kt + 1 < NKT) { CP_WAIT(1); } else { CP_WAIT(0); }
        __syncthreads();
        if (kt + 2 < NKT) issue(kt + 2, (kt + 2) % 3);

        const uint32_t abase = sbase + (kt % 3) * 32768;
        const uint32_t bbase = abase + 16384;
        #pragma unroll
        for (int ks = 0; ks < 4; ks++) {
            uint32_t a[4][4], b[4][2];
            #pragma unroll
            for (int mt = 0; mt < 4; mt++) {
                const int row = wm + mt * 16 + (lane & 7) + ((lane >> 3) & 1) * 8;
                const int ch  = ks * 2 + (lane >> 4);
                const uint32_t ad = abase + row * 128 + (((uint32_t)(ch ^ (row & 7))) << 4);
                LDSM_X4(a[mt][0], a[mt][1], a[mt][2], a[mt][3], ad);
            }
            #pragma unroll
            for (int p = 0; p < 2; p++) {
                const int row = wn + p * 16 + (lane & 7) + (lane >> 4) * 8;
                const int ch  = ks * 2 + ((lane >> 3) & 1);
                const uint32_t bd = bbase + row * 128 + (((uint32_t)(ch ^ (row & 7))) << 4);
                LDSM_X4(b[2*p][0], b[2*p][1], b[2*p+1][0], b[2*p+1][1], bd);
            }
            #pragma unroll
            for (int mt = 0; mt < 4; mt++)
                #pragma unroll
                for (int nt = 0; nt < 4; nt++)
                    mma_tf32(c[mt][nt], a[mt], b[nt]);
        }
    }

    const int mbase = m0 + wm + (lane >> 2);
    const int nbase = n0 + wn + (lane & 3) * 2;
    if (mode == 1) {
        __half* Ch = (__half*)Cv;
        #pragma unroll
        for (int mt = 0; mt < 4; mt++) {
            #pragma unroll
            for (int nt = 0; nt < 4; nt++) {
                *(half2*)(Ch + (size_t)(mbase + mt*16)     * 1024 + nbase + nt*8) =
                    __floats2half2_rn(c[mt][nt][0], c[mt][nt][1]);
                *(half2*)(Ch + (size_t)(mbase + mt*16 + 8) * 1024 + nbase + nt*8) =
                    __floats2half2_rn(c[mt][nt][2], c[mt][nt][3]);
            }
        }
    } else {
        float* C = (float*)Cv;
        #pragma unroll
        for (int mt = 0; mt < 4; mt++) {
            #pragma unroll
            for (int nt = 0; nt < 4; nt++) {
                float* p0 = C + (size_t)(mbase + mt*16)     * 1024 + nbase + nt*8;
                float* p1 = C + (size_t)(mbase + mt*16 + 8) * 1024 + nbase + nt*8;
                *(float2*)p0 = make_float2(c[mt][nt][0], c[mt][nt][1]);
                *(float2*)p1 = make_float2(c[mt][nt][2], c[mt][nt][3]);
            }
        }
    }
}

// Fused QKV projections: blockIdx.z selects (A, B, C).
__global__ __launch_bounds__(256, 2) void gemm_qkv(
    const float* __restrict__ A0, const float* __restrict__ A1, const float* __restrict__ A2,
    const float* __restrict__ B0, const float* __restrict__ B1, const float* __restrict__ B2,
    __half* __restrict__ C0, __half* __restrict__ C1, __half* __restrict__ C2)
{
    extern __shared__ char sm[];
    const int z = blockIdx.z;
    const float* A = z == 0 ? A0 : z == 1 ? A1 : A2;
    const float* B = z == 0 ? B0 : z == 1 ? B1 : B2;
    __half* C      = z == 0 ? C0 : z == 1 ? C1 : C2;
    gemm_body(A, B, C, 1, sm);
}

__global__ __launch_bounds__(256, 2) void gemm_tc(
    const float* __restrict__ A, const float* __restrict__ B,
    float* __restrict__ C, int mode)
{
    extern __shared__ char sm[];
    gemm_body(A, B, C, mode, sm);
}

// ======================================================================
// Flash attention v7 (fp16 MMA m16n8k16, fp32 softmax/accum).
// BQ=128, 8 warps/CTA, 2 CTAs/SM (48 KB smem). K/V double-buffered via
// cp.async, end-of-iteration prefetch. V consumed in NATURAL [kv][d]
// layout via ldmatrix.trans (no V^T needed). P fp16 overlays Q staging.
// Smem bytes: K0 8K | K1 8K | V0 8K | V1 8K | PQ 16K = 48 KB. Rows 128B,
// XOR-swizzled 16B chunks (c ^= row&7) for conflict-free ldmatrix.
// ======================================================================
#define KOFF(buf)  ((buf) * 8192)
#define VOFF(buf)  (16384 + (buf) * 8192)
#define POFF       32768
#define FLASH_SMEM 49152
#define SM_SCALE_LOG2E 0.1803368801111204f   // 0.125 * log2(e)

__global__ __launch_bounds__(256, 2) void flash_tc(
    const __half* __restrict__ Qp, const __half* __restrict__ Kp,
    const __half* __restrict__ Vp, float* __restrict__ Op)
{
    extern __shared__ char fsc[];
    const uint32_t sb = smem_u32(fsc);
    const int tid = threadIdx.x, lane = tid & 31, w = tid >> 5;
    const int b = blockIdx.z, h = blockIdx.y;
    const int q0 = blockIdx.x * 128;

    const __half* Qg = Qp + ((size_t)b * SEQ + q0) * D_MODEL + h * DKH;
    const __half* Kg = Kp + (size_t)b * SEQ * D_MODEL + h * DKH;
    const __half* Vg = Vp + (size_t)b * SEQ * D_MODEL + h * DKH;

    auto issueKV = [&](int kt, int buf) {
        #pragma unroll
        for (int i = 0; i < 2; i++) {
            const int id = tid + 256 * i;
            const int row = id >> 3, cx = id & 7;
            const uint32_t off = row * 128 + (((uint32_t)(cx ^ (row & 7))) << 4);
            CP16(sb + KOFF(buf) + off, Kg + (size_t)(kt * 64 + row) * D_MODEL + cx * 8);
            CP16(sb + VOFF(buf) + off, Vg + (size_t)(kt * 64 + row) * D_MODEL + cx * 8);
        }
        CP_COMMIT();
    };

    // prologue: Q (128 rows x 128B into PQ) + K0/V0, then K1/V1
    #pragma unroll
    for (int i = 0; i < 4; i++) {
        const int id = tid + 256 * i;
        const int row = id >> 3, cx = id & 7;
        const uint32_t off = row * 128 + (((uint32_t)(cx ^ (row & 7))) << 4);
        CP16(sb + POFF + off, Qg + (size_t)row * D_MODEL + cx * 8);
    }
    issueKV(0, 0);
    issueKV(1, 1);

    float o[8][4];
    #pragma unroll
    for (int nt = 0; nt < 8; nt++)
        #pragma unroll
        for (int j = 0; j < 4; j++) o[nt][j] = 0.f;
    float m0r = -1e30f, m1r = -1e30f, l0r = 0.f, l1r = 0.f;
    uint32_t qf[4][4];   // Q fragments, m16 x k64 (4 k16 chunks)

    // per-lane row patterns
    const int arow = w * 16 + (lane & 7) + ((lane >> 3) & 1) * 8;    // A-frag rows (Q/P)
    const uint32_t arow_off = (uint32_t)arow * 128;
    const int asw = arow & 7;
    const int achsel = lane >> 4;                                     // +0/+1 chunk

    const int NKT = SEQ / 64;
    for (int kt = 0; kt < NKT; kt++) {
        if (kt + 1 < NKT) { CP_WAIT(1); } else { CP_WAIT(0); }
        __syncthreads();

        if (kt == 0) {   // hoist Q fragments before P overlays the region
            #pragma unroll
            for (int ks = 0; ks < 4; ks++) {
                const uint32_t ad = sb + POFF + arow_off +
                    (((uint32_t)((2 * ks + achsel) ^ asw)) << 4);
                LDSM_X4(qf[ks][0], qf[ks][1], qf[ks][2], qf[ks][3], ad);
            }
        }

        const int buf = kt & 1;
        const uint32_t Kb = sb + KOFF(buf);
        const uint32_t Vb = sb + VOFF(buf);

        // ---- S = Q K^T  (m16 x n64, k=64; 4 k16 steps) ----
        float sf[8][4];
        #pragma unroll
        for (int nt = 0; nt < 8; nt++)
            #pragma unroll
            for (int j = 0; j < 4; j++) sf[nt][j] = 0.f;

        #pragma unroll
        for (int ks = 0; ks < 4; ks++) {
            #pragma unroll
            for (int pp = 0; pp < 4; pp++) {
                // non-trans ldmatrix on K [kv][d]: nt pair (2pp, 2pp+1)
                const int krow = (2 * pp + ((lane >> 4) & 1)) * 8 + (lane & 7);
                const int kch  = 2 * ks + ((lane >> 3) & 1);
                const uint32_t bd = Kb + (uint32_t)krow * 128 +
                    (((uint32_t)(kch ^ (krow & 7))) << 4);
                uint32_t b0, b1, b2, b3;
                LDSM_X4(b0, b1, b2, b3, bd);
                mma_f16(sf[2*pp],     qf[ks], b0, b1);
                mma_f16(sf[2*pp + 1], qf[ks], b2, b3);
            }
        }

        // ---- online softmax: p = 2^((s - m) * 0.125*log2e) ----
        float mn0 = m0r, mn1 = m1r;
        #pragma unroll
        for (int nt = 0; nt < 8; nt++) {
            mn0 = fmaxf(mn0, fmaxf(sf[nt][0], sf[nt][1]));
            mn1 = fmaxf(mn1, fmaxf(sf[nt][2], sf[nt][3]));
        }
        mn0 = fmaxf(mn0, __shfl_xor_sync(0xffffffffu, mn0, 1));
        mn0 = fmaxf(mn0, __shfl_xor_sync(0xffffffffu, mn0, 2));
        mn1 = fmaxf(mn1, __shfl_xor_sync(0xffffffffu, mn1, 1));
        mn1 = fmaxf(mn1, __shfl_xor_sync(0xffffffffu, mn1, 2));
        const float corr0 = ex2f((m0r - mn0) * SM_SCALE_LOG2E);
        const float corr1 = ex2f((m1r - mn1) * SM_SCALE_LOG2E);
        m0r = mn0; m1r = mn1;
        const float nc0 = -mn0 * SM_SCALE_LOG2E;
        const float nc1 = -mn1 * SM_SCALE_LOG2E;

        float rs0 = 0.f, rs1 = 0.f;
        #pragma unroll
        for (int nt = 0; nt < 8; nt++) {
            sf[nt][0] = ex2f(fmaf(sf[nt][0], SM_SCALE_LOG2E, nc0));
            sf[nt][1] = ex2f(fmaf(sf[nt][1], SM_SCALE_LOG2E, nc0));
            sf[nt][2] = ex2f(fmaf(sf[nt][2], SM_SCALE_LOG2E, nc1));
            sf[nt][3] = ex2f(fmaf(sf[nt][3], SM_SCALE_LOG2E, nc1));
            rs0 += sf[nt][0] + sf[nt][1];
            rs1 += sf[nt][2] + sf[nt][3];
        }
        rs0 += __shfl_xor_sync(0xffffffffu, rs0, 1);
        rs0 += __shfl_xor_sync(0xffffffffu, rs0, 2);
        rs1 += __shfl_xor_sync(0xffffffffu, rs1, 1);
        rs1 += __shfl_xor_sync(0xffffffffu, rs1, 2);
        l0r = l0r * corr0 + rs0;
        l1r = l1r * corr1 + rs1;
        #pragma unroll
        for (int nt = 0; nt < 8; nt++) {
            o[nt][0] *= corr0; o[nt][1] *= corr0;
            o[nt][2] *= corr1; o[nt][3] *= corr1;
        }

        // ---- P (fp16) -> PQ region, warp-private rows ----
        {
            const int r0 = w * 16 + (lane >> 2);
            const int r1 = r0 + 8;
            const uint32_t cc4 = (uint32_t)(lane & 3) * 4;
            #pragma unroll
            for (int nt = 0; nt < 8; nt++) {
                *(half2*)(fsc + POFF + r0 * 128 +
                          (((uint32_t)(nt ^ (r0 & 7))) << 4) + cc4) =
                    __floats2half2_rn(sf[nt][0], sf[nt][1]);
                *(half2*)(fsc + POFF + r1 * 128 +
                          (((uint32_t)(nt ^ (r1 & 7))) << 4) + cc4) =
                    __floats2half2_rn(sf[nt][2], sf[nt][3]);
            }
        }
        __syncwarp();

        // ---- O += P V  (A = P m16 x k64, B = V [kv][d] via trans) ----
        #pragma unroll
        for (int ks = 0; ks < 4; ks++) {
            uint32_t pf[4];
            const uint32_t pd = sb + POFF + arow_off +
                (((uint32_t)((2 * ks + achsel) ^ asw)) << 4);
            LDSM_X4(pf[0], pf[1], pf[2], pf[3], pd);
            #pragma unroll
            for (int pp = 0; pp < 4; pp++) {
                const int vrow = ks * 16 + (lane & 7) + ((lane >> 3) & 1) * 8;
                const int vch  = 2 * pp + ((lane >> 4) & 1);
                const uint32_t vd = Vb + (uint32_t)vrow * 128 +
                    (((uint32_t)(vch ^ (vrow & 7))) << 4);
                uint32_t b0, b1, b2, b3;
                LDSM_X4_T(b0, b1, b2, b3, vd);
                mma_f16(o[2*pp],     pf, b0, b1);
                mma_f16(o[2*pp + 1], pf, b2, b3);
            }
        }

        // prefetch tile kt+2 into buf (kt&1) — fully consumed now
        if (kt + 2 < NKT) {
            __syncthreads();
            issueKV(kt + 2, buf);
        }
    }

    // epilogue: normalize, tf32-round, write Ct (fp32)
    const float inv0 = 1.f / l0r, inv1 = 1.f / l1r;
    const int row0 = q0 + w * 16 + (lane >> 2);
    const int col  = h * DKH + (lane & 3) * 2;
    float* Ob = Op + (size_t)b * SEQ * D_MODEL;
    #pragma unroll
    for (int nt = 0; nt < 8; nt++) {
        *(float2*)(Ob + (size_t)row0 * D_MODEL + col + nt * 8) =
            make_float2(tf32f(o[nt][0] * inv0), tf32f(o[nt][1] * inv0));
        *(float2*)(Ob + (size_t)(row0 + 8) * D_MODEL + col + nt * 8) =
            make_float2(tf32f(o[nt][2] * inv1), tf32f(o[nt][3] * inv1));
    }
}

// ======================================================================
extern "C" void kernel_launch(void* const* d_in, const int* in_sizes, int n_in,
                              void* d_out, int out_size)
{
    (void)in_sizes; (void)n_in; (void)out_size;
    const float* Q_in = (const float*)d_in[0];
    const float* K_in = (const float*)d_in[1];
    const float* V_in = (const float*)d_in[2];
    const float* W_q  = (const float*)d_in[3];
    const float* W_k  = (const float*)d_in[4];
    const float* W_v  = (const float*)d_in[5];
    const float* W_o  = (const float*)d_in[6];
    float* out = (float*)d_out;

    __half *Qp, *Kp, *Vp;
    float *Ct, *rQ, *rK, *rV, *rWq, *rWk, *rWv, *rWo;
    cudaGetSymbolAddress((void**)&Qp, g_Qp);
    cudaGetSymbolAddress((void**)&Kp, g_Kp);
    cudaGetSymbolAddress((void**)&Vp, g_Vp);
    cudaGetSymbolAddress((void**)&Ct, g_Ct);
    cudaGetSymbolAddress((void**)&rQ, g_rQ);
    cudaGetSymbolAddress((void**)&rK, g_rK);
    cudaGetSymbolAddress((void**)&rV, g_rV);
    cudaGetSymbolAddress((void**)&rWq, g_rWq);
    cudaGetSymbolAddress((void**)&rWk, g_rWk);
    cudaGetSymbolAddress((void**)&rWv, g_rWv);
    cudaGetSymbolAddress((void**)&rWo, g_rWo);

    cudaFuncSetAttribute(gemm_qkv, cudaFuncAttributeMaxDynamicSharedMemorySize, GEMM_SMEM);
    cudaFuncSetAttribute(gemm_tc, cudaFuncAttributeMaxDynamicSharedMemorySize, GEMM_SMEM);
    cudaFuncSetAttribute(flash_tc, cudaFuncAttributeMaxDynamicSharedMemorySize, FLASH_SMEM);

    round_all<<<(NTOT4 + 255) / 256, 256>>>(Q_in, K_in, V_in, W_q, W_k, W_v, W_o,
                                            rQ, rK, rV, rWq, rWk, rWv, rWo);

    gemm_qkv<<<dim3(8, 64, 3), 256, GEMM_SMEM>>>(rQ, rK, rV, rWq, rWk, rWv, Qp, Kp, Vp);

    flash_tc<<<dim3(SEQ / 128, NHEAD, BATCH), 256, FLASH_SMEM>>>(Qp, Kp, Vp, Ct);

    gemm_tc<<<dim3(8, 64), 256, GEMM_SMEM>>>(Ct, rWo, out, 0);
}

// round 11
// speedup vs baseline: 8.0764x; 1.3533x over previous
#include <cuda_runtime.h>
#include <cuda_fp16.h>
#include <cstdint>

#define D_MODEL 1024
#define NHEAD   16
#define DKH     64
#define BATCH   4
#define SEQ     2048
#define MTOT    (BATCH*SEQ)   // 8192

// Scratch: projected Q/K/V + attention concat in fp16, all [b][s][h*d].
__device__ __half g_Qp[(size_t)MTOT * D_MODEL];
__device__ __half g_Kp[(size_t)MTOT * D_MODEL];
__device__ __half g_Vp[(size_t)MTOT * D_MODEL];
__device__ __half g_Ct[(size_t)MTOT * D_MODEL];
// fp16-RN pre-rounded copies (cp.async path cannot convert)
__device__ __half g_rQ[(size_t)MTOT * D_MODEL];
__device__ __half g_rK[(size_t)MTOT * D_MODEL];
__device__ __half g_rV[(size_t)MTOT * D_MODEL];
__device__ __half g_rWq[(size_t)D_MODEL * D_MODEL];
__device__ __half g_rWk[(size_t)D_MODEL * D_MODEL];
__device__ __half g_rWv[(size_t)D_MODEL * D_MODEL];
__device__ __half g_rWo[(size_t)D_MODEL * D_MODEL];

// ---------------- PTX helpers ----------------
__device__ __forceinline__ float ex2f(float x) {
    float y;
    asm("ex2.approx.f32 %0, %1;" : "=f"(y) : "f"(x));
    return y;
}
__device__ __forceinline__ uint32_t smem_u32(const void* p) {
    uint32_t a;
    asm("{ .reg .u64 t; cvta.to.shared.u64 t, %1; cvt.u32.u64 %0, t; }" : "=r"(a) : "l"(p));
    return a;
}
__device__ __forceinline__ void mma_f16(float c[4], const uint32_t a[4],
                                        uint32_t b0, uint32_t b1) {
    asm volatile(
        "mma.sync.aligned.m16n8k16.row.col.f32.f16.f16.f32 "
        "{%0,%1,%2,%3}, {%4,%5,%6,%7}, {%8,%9}, {%0,%1,%2,%3};"
        : "+f"(c[0]), "+f"(c[1]), "+f"(c[2]), "+f"(c[3])
        : "r"(a[0]), "r"(a[1]), "r"(a[2]), "r"(a[3]), "r"(b0), "r"(b1));
}
#define LDSM_X4(r0,r1,r2,r3,addr) \
    asm volatile("ldmatrix.sync.aligned.m8n8.x4.shared.b16 {%0,%1,%2,%3}, [%4];" \
        : "=r"(r0),"=r"(r1),"=r"(r2),"=r"(r3) : "r"(addr))
#define LDSM_X4_T(r0,r1,r2,r3,addr) \
    asm volatile("ldmatrix.sync.aligned.m8n8.x4.trans.shared.b16 {%0,%1,%2,%3}, [%4];" \
        : "=r"(r0),"=r"(r1),"=r"(r2),"=r"(r3) : "r"(addr))
#define CP16(sa, ga)  asm volatile("cp.async.cg.shared.global [%0], [%1], 16;" :: "r"(sa), "l"(ga))
#define CP_COMMIT()   asm volatile("cp.async.commit_group;" ::: "memory")
#define CP_WAIT(n)    asm volatile("cp.async.wait_group %0;" :: "n"(n) : "memory")

// ---------------- fused fp16-RN rounding pass ----------------
#define NB4 (MTOT * D_MODEL / 4)
#define NW4 (D_MODEL * D_MODEL / 4)
#define NTOT4 (3 * NB4 + 4 * NW4)

__global__ void round_all(
    const float* __restrict__ Qi, const float* __restrict__ Ki, const float* __restrict__ Vi,
    const float* __restrict__ Wq, const float* __restrict__ Wk,
    const float* __restrict__ Wv, const float* __restrict__ Wo,
    __half* __restrict__ rQ, __half* __restrict__ rK, __half* __restrict__ rV,
    __half* __restrict__ rWq, __half* __restrict__ rWk, __half* __restrict__ rWv,
    __half* __restrict__ rWo)
{
    const int i = blockIdx.x * blockDim.x + threadIdx.x;
    if (i >= NTOT4) return;
    const float4* src;
    __half* dst;
    int off;
    if (i < 3 * NB4) {
        const int seg = i / NB4;
        off = i - seg * NB4;
        src = (const float4*)(seg == 0 ? Qi : seg == 1 ? Ki : Vi);
        dst = seg == 0 ? rQ : seg == 1 ? rK : rV;
    } else {
        const int j = i - 3 * NB4;
        const int seg = j / NW4;
        off = j - seg * NW4;
        src = (const float4*)(seg == 0 ? Wq : seg == 1 ? Wk : seg == 2 ? Wv : Wo);
        dst = seg == 0 ? rWq : seg == 1 ? rWk : seg == 2 ? rWv : rWo;
    }
    float4 v = src[off];
    half2 h0 = __floats2half2_rn(v.x, v.y);
    half2 h1 = __floats2half2_rn(v.z, v.w);
    uint2 u;
    u.x = *(uint32_t*)&h0;
    u.y = *(uint32_t*)&h1;
    *(uint2*)(dst + 4 * (size_t)off) = u;
}

// ======================================================================
// fp16 GEMM core (NT): C[8192,1024] = A * B^T. 128x128 tile, BK=64
// (128B rows), 3-stage cp.async, ldmatrix, m16n8k16 MMA.
// mode 0: raw fp32 out. mode 1: fp16 out.
// ======================================================================
#define GEMM_SMEM (3 * 32768)

__device__ __forceinline__ void gemm_body(
    const __half* __restrict__ A, const __half* __restrict__ B,
    void* __restrict__ Cv, int mode, char* sm)
{
    const uint32_t sbase = smem_u32(sm);
    const int tid = threadIdx.x, lane = tid & 31, wid = tid >> 5;
    const int wm = (wid & 1) * 64, wn = (wid >> 1) * 32;
    const int m0 = blockIdx.y * 128, n0 = blockIdx.x * 128;

    float c[4][4][4];
    #pragma unroll
    for (int i = 0; i < 4; i++)
        #pragma unroll
        for (int j = 0; j < 4; j++)
            #pragma unroll
            for (int r = 0; r < 4; r++) c[i][j][r] = 0.f;

    auto issue = [&](int kt, int buf) {
        #pragma unroll
        for (int i = 0; i < 4; i++) {
            const int id = tid + 256 * i;
            const int row = id >> 3, cx = id & 7;
            const uint32_t off = row * 128 + (((uint32_t)(cx ^ (row & 7))) << 4);
            const __half* ga = A + (size_t)(m0 + row) * 1024 + kt * 64 + cx * 8;
            const __half* gb = B + (size_t)(n0 + row) * 1024 + kt * 64 + cx * 8;
            CP16(sbase + buf * 32768 + off, ga);
            CP16(sbase + buf * 32768 + 16384 + off, gb);
        }
        CP_COMMIT();
    };

    issue(0, 0);
    issue(1, 1);

    const int NKT = 16;
    for (int kt = 0; kt < NKT; kt++) {
        if (kt + 1 < NKT) { CP_WAIT(1); } else { CP_WAIT(0); }
        __syncthreads();
        if (kt + 2 < NKT) issue(kt + 2, (kt + 2) % 3);

        const uint32_t abase = sbase + (kt % 3) * 32768;
        const uint32_t bbase = abase + 16384;
        #pragma unroll
        for (int ks = 0; ks < 4; ks++) {            // 4 x k16 per BK=64 tile
            uint32_t a[4][4];
            #pragma unroll
            for (int mt = 0; mt < 4; mt++) {
                const int row = wm + mt * 16 + (lane & 7) + ((lane >> 3) & 1) * 8;
                const int ch  = 2 * ks + (lane >> 4);
                const uint32_t ad = abase + row * 128 + (((uint32_t)(ch ^ (row & 7))) << 4);
                LDSM_X4(a[mt][0], a[mt][1], a[mt][2], a[mt][3], ad);
            }
            #pragma unroll
            for (int p = 0; p < 2; p++) {
                const int row = wn + p * 16 + ((lane >> 4) & 1) * 8 + (lane & 7);
                const int ch  = 2 * ks + ((lane >> 3) & 1);
                const uint32_t bd = bbase + row * 128 + (((uint32_t)(ch ^ (row & 7))) << 4);
                uint32_t b0, b1, b2, b3;
                LDSM_X4(b0, b1, b2, b3, bd);
                #pragma unroll
                for (int mt = 0; mt < 4; mt++) {
                    mma_f16(c[mt][2*p],     a[mt], b0, b1);
                    mma_f16(c[mt][2*p + 1], a[mt], b2, b3);
                }
            }
        }
    }

    const int mbase = m0 + wm + (lane >> 2);
    const int nbase = n0 + wn + (lane & 3) * 2;
    if (mode == 1) {
        __half* Ch = (__half*)Cv;
        #pragma unroll
        for (int mt = 0; mt < 4; mt++) {
            #pragma unroll
            for (int nt = 0; nt < 4; nt++) {
                *(half2*)(Ch + (size_t)(mbase + mt*16)     * 1024 + nbase + nt*8) =
                    __floats2half2_rn(c[mt][nt][0], c[mt][nt][1]);
                *(half2*)(Ch + (size_t)(mbase + mt*16 + 8) * 1024 + nbase + nt*8) =
                    __floats2half2_rn(c[mt][nt][2], c[mt][nt][3]);
            }
        }
    } else {
        float* C = (float*)Cv;
        #pragma unroll
        for (int mt = 0; mt < 4; mt++) {
            #pragma unroll
            for (int nt = 0; nt < 4; nt++) {
                float* p0 = C + (size_t)(mbase + mt*16)     * 1024 + nbase + nt*8;
                float* p1 = C + (size_t)(mbase + mt*16 + 8) * 1024 + nbase + nt*8;
                *(float2*)p0 = make_float2(c[mt][nt][0], c[mt][nt][1]);
                *(float2*)p1 = make_float2(c[mt][nt][2], c[mt][nt][3]);
            }
        }
    }
}

// Fused QKV projections: blockIdx.z selects (A, B, C).
__global__ __launch_bounds__(256, 2) void gemm_qkv(
    const __half* __restrict__ A0, const __half* __restrict__ A1, const __half* __restrict__ A2,
    const __half* __restrict__ B0, const __half* __restrict__ B1, const __half* __restrict__ B2,
    __half* __restrict__ C0, __half* __restrict__ C1, __half* __restrict__ C2)
{
    extern __shared__ char sm[];
    const int z = blockIdx.z;
    const __half* A = z == 0 ? A0 : z == 1 ? A1 : A2;
    const __half* B = z == 0 ? B0 : z == 1 ? B1 : B2;
    __half* C       = z == 0 ? C0 : z == 1 ? C1 : C2;
    gemm_body(A, B, C, 1, sm);
}

__global__ __launch_bounds__(256, 2) void gemm_tc(
    const __half* __restrict__ A, const __half* __restrict__ B,
    float* __restrict__ C, int mode)
{
    extern __shared__ char sm[];
    gemm_body(A, B, C, mode, sm);
}

// ======================================================================
// Flash attention v7 (fp16 MMA m16n8k16, fp32 softmax/accum) — same as
// R10 except the epilogue writes fp16 Ct.
// ======================================================================
#define KOFF(buf)  ((buf) * 8192)
#define VOFF(buf)  (16384 + (buf) * 8192)
#define POFF       32768
#define FLASH_SMEM 49152
#define SM_SCALE_LOG2E 0.1803368801111204f   // 0.125 * log2(e)

__global__ __launch_bounds__(256, 2) void flash_tc(
    const __half* __restrict__ Qp, const __half* __restrict__ Kp,
    const __half* __restrict__ Vp, __half* __restrict__ Op)
{
    extern __shared__ char fsc[];
    const uint32_t sb = smem_u32(fsc);
    const int tid = threadIdx.x, lane = tid & 31, w = tid >> 5;
    const int b = blockIdx.z, h = blockIdx.y;
    const int q0 = blockIdx.x * 128;

    const __half* Qg = Qp + ((size_t)b * SEQ + q0) * D_MODEL + h * DKH;
    const __half* Kg = Kp + (size_t)b * SEQ * D_MODEL + h * DKH;
    const __half* Vg = Vp + (size_t)b * SEQ * D_MODEL + h * DKH;

    auto issueKV = [&](int kt, int buf) {
        #pragma unroll
        for (int i = 0; i < 2; i++) {
            const int id = tid + 256 * i;
            const int row = id >> 3, cx = id & 7;
            const uint32_t off = row * 128 + (((uint32_t)(cx ^ (row & 7))) << 4);
            CP16(sb + KOFF(buf) + off, Kg + (size_t)(kt * 64 + row) * D_MODEL + cx * 8);
            CP16(sb + VOFF(buf) + off, Vg + (size_t)(kt * 64 + row) * D_MODEL + cx * 8);
        }
        CP_COMMIT();
    };

    #pragma unroll
    for (int i = 0; i < 4; i++) {
        const int id = tid + 256 * i;
        const int row = id >> 3, cx = id & 7;
        const uint32_t off = row * 128 + (((uint32_t)(cx ^ (row & 7))) << 4);
        CP16(sb + POFF + off, Qg + (size_t)row * D_MODEL + cx * 8);
    }
    issueKV(0, 0);
    issueKV(1, 1);

    float o[8][4];
    #pragma unroll
    for (int nt = 0; nt < 8; nt++)
        #pragma unroll
        for (int j = 0; j < 4; j++) o[nt][j] = 0.f;
    float m0r = -1e30f, m1r = -1e30f, l0r = 0.f, l1r = 0.f;
    uint32_t qf[4][4];

    const int arow = w * 16 + (lane & 7) + ((lane >> 3) & 1) * 8;
    const uint32_t arow_off = (uint32_t)arow * 128;
    const int asw = arow & 7;
    const int achsel = lane >> 4;

    const int NKT = SEQ / 64;
    for (int kt = 0; kt < NKT; kt++) {
        if (kt + 1 < NKT) { CP_WAIT(1); } else { CP_WAIT(0); }
        __syncthreads();

        if (kt == 0) {
            #pragma unroll
            for (int ks = 0; ks < 4; ks++) {
                const uint32_t ad = sb + POFF + arow_off +
                    (((uint32_t)((2 * ks + achsel) ^ asw)) << 4);
                LDSM_X4(qf[ks][0], qf[ks][1], qf[ks][2], qf[ks][3], ad);
            }
        }

        const int buf = kt & 1;
        const uint32_t Kb = sb + KOFF(buf);
        const uint32_t Vb = sb + VOFF(buf);

        float sf[8][4];
        #pragma unroll
        for (int nt = 0; nt < 8; nt++)
            #pragma unroll
            for (int j = 0; j < 4; j++) sf[nt][j] = 0.f;

        #pragma unroll
        for (int ks = 0; ks < 4; ks++) {
            #pragma unroll
            for (int pp = 0; pp < 4; pp++) {
                const int krow = (2 * pp + ((lane >> 4) & 1)) * 8 + (lane & 7);
                const int kch  = 2 * ks + ((lane >> 3) & 1);
                const uint32_t bd = Kb + (uint32_t)krow * 128 +
                    (((uint32_t)(kch ^ (krow & 7))) << 4);
                uint32_t b0, b1, b2, b3;
                LDSM_X4(b0, b1, b2, b3, bd);
                mma_f16(sf[2*pp],     qf[ks], b0, b1);
                mma_f16(sf[2*pp + 1], qf[ks], b2, b3);
            }
        }

        float mn0 = m0r, mn1 = m1r;
        #pragma unroll
        for (int nt = 0; nt < 8; nt++) {
            mn0 = fmaxf(mn0, fmaxf(sf[nt][0], sf[nt][1]));
            mn1 = fmaxf(mn1, fmaxf(sf[nt][2], sf[nt][3]));
        }
        mn0 = fmaxf(mn0, __shfl_xor_sync(0xffffffffu, mn0, 1));
        mn0 = fmaxf(mn0, __shfl_xor_sync(0xffffffffu, mn0, 2));
        mn1 = fmaxf(mn1, __shfl_xor_sync(0xffffffffu, mn1, 1));
        mn1 = fmaxf(mn1, __shfl_xor_sync(0xffffffffu, mn1, 2));
        const float corr0 = ex2f((m0r - mn0) * SM_SCALE_LOG2E);
        const float corr1 = ex2f((m1r - mn1) * SM_SCALE_LOG2E);
        m0r = mn0; m1r = mn1;
        const float nc0 = -mn0 * SM_SCALE_LOG2E;
        const float nc1 = -mn1 * SM_SCALE_LOG2E;

        float rs0 = 0.f, rs1 = 0.f;
        #pragma unroll
        for (int nt = 0; nt < 8; nt++) {
            sf[nt][0] = ex2f(fmaf(sf[nt][0], SM_SCALE_LOG2E, nc0));
            sf[nt][1] = ex2f(fmaf(sf[nt][1], SM_SCALE_LOG2E, nc0));
            sf[nt][2] = ex2f(fmaf(sf[nt][2], SM_SCALE_LOG2E, nc1));
            sf[nt][3] = ex2f(fmaf(sf[nt][3], SM_SCALE_LOG2E, nc1));
            rs0 += sf[nt][0] + sf[nt][1];
            rs1 += sf[nt][2] + sf[nt][3];
        }
        rs0 += __shfl_xor_sync(0xffffffffu, rs0, 1);
        rs0 += __shfl_xor_sync(0xffffffffu, rs0, 2);
        rs1 += __shfl_xor_sync(0xffffffffu, rs1, 1);
        rs1 += __shfl_xor_sync(0xffffffffu, rs1, 2);
        l0r = l0r * corr0 + rs0;
        l1r = l1r * corr1 + rs1;
        #pragma unroll
        for (int nt = 0; nt < 8; nt++) {
            o[nt][0] *= corr0; o[nt][1] *= corr0;
            o[nt][2] *= corr1; o[nt][3] *= corr1;
        }

        {
            const int r0 = w * 16 + (lane >> 2);
            const int r1 = r0 + 8;
            const uint32_t cc4 = (uint32_t)(lane & 3) * 4;
            #pragma unroll
            for (int nt = 0; nt < 8; nt++) {
                *(half2*)(fsc + POFF + r0 * 128 +
                          (((uint32_t)(nt ^ (r0 & 7))) << 4) + cc4) =
                    __floats2half2_rn(sf[nt][0], sf[nt][1]);
                *(half2*)(fsc + POFF + r1 * 128 +
                          (((uint32_t)(nt ^ (r1 & 7))) << 4) + cc4) =
                    __floats2half2_rn(sf[nt][2], sf[nt][3]);
            }
        }
        __syncwarp();

        #pragma unroll
        for (int ks = 0; ks < 4; ks++) {
            uint32_t pf[4];
            const uint32_t pd = sb + POFF + arow_off +
                (((uint32_t)((2 * ks + achsel) ^ asw)) << 4);
            LDSM_X4(pf[0], pf[1], pf[2], pf[3], pd);
            #pragma unroll
            for (int pp = 0; pp < 4; pp++) {
                const int vrow = ks * 16 + (lane & 7) + ((lane >> 3) & 1) * 8;
                const int vch  = 2 * pp + ((lane >> 4) & 1);
                const uint32_t vd = Vb + (uint32_t)vrow * 128 +
                    (((uint32_t)(vch ^ (vrow & 7))) << 4);
                uint32_t b0, b1, b2, b3;
                LDSM_X4_T(b0, b1, b2, b3, vd);
                mma_f16(o[2*pp],     pf, b0, b1);
                mma_f16(o[2*pp + 1], pf, b2, b3);
            }
        }

        if (kt + 2 < NKT) {
            __syncthreads();
            issueKV(kt + 2, buf);
        }
    }

    // epilogue: normalize, fp16-round, write Ct (fp16)
    const float inv0 = 1.f / l0r, inv1 = 1.f / l1r;
    const int row0 = q0 + w * 16 + (lane >> 2);
    const int col  = h * DKH + (lane & 3) * 2;
    __half* Ob = Op + (size_t)b * SEQ * D_MODEL;
    #pragma unroll
    for (int nt = 0; nt < 8; nt++) {
        *(half2*)(Ob + (size_t)row0 * D_MODEL + col + nt * 8) =
            __floats2half2_rn(o[nt][0] * inv0, o[nt][1] * inv0);
        *(half2*)(Ob + (size_t)(row0 + 8) * D_MODEL + col + nt * 8) =
            __floats2half2_rn(o[nt][2] * inv1, o[nt][3] * inv1);
    }
}

// ======================================================================
extern "C" void kernel_launch(void* const* d_in, const int* in_sizes, int n_in,
                              void* d_out, int out_size)
{
    (void)in_sizes; (void)n_in; (void)out_size;
    const float* Q_in = (const float*)d_in[0];
    const float* K_in = (const float*)d_in[1];
    const float* V_in = (const float*)d_in[2];
    const float* W_q  = (const float*)d_in[3];
    const float* W_k  = (const float*)d_in[4];
    const float* W_v  = (const float*)d_in[5];
    const float* W_o  = (const float*)d_in[6];
    float* out = (float*)d_out;

    __half *Qp, *Kp, *Vp, *Ct, *rQ, *rK, *rV, *rWq, *rWk, *rWv, *rWo;
    cudaGetSymbolAddress((void**)&Qp, g_Qp);
    cudaGetSymbolAddress((void**)&Kp, g_Kp);
    cudaGetSymbolAddress((void**)&Vp, g_Vp);
    cudaGetSymbolAddress((void**)&Ct, g_Ct);
    cudaGetSymbolAddress((void**)&rQ, g_rQ);
    cudaGetSymbolAddress((void**)&rK, g_rK);
    cudaGetSymbolAddress((void**)&rV, g_rV);
    cudaGetSymbolAddress((void**)&rWq, g_rWq);
    cudaGetSymbolAddress((void**)&rWk, g_rWk);
    cudaGetSymbolAddress((void**)&rWv, g_rWv);
    cudaGetSymbolAddress((void**)&rWo, g_rWo);

    cudaFuncSetAttribute(gemm_qkv, cudaFuncAttributeMaxDynamicSharedMemorySize, GEMM_SMEM);
    cudaFuncSetAttribute(gemm_tc, cudaFuncAttributeMaxDynamicSharedMemorySize, GEMM_SMEM);
    cudaFuncSetAttribute(flash_tc, cudaFuncAttributeMaxDynamicSharedMemorySize, FLASH_SMEM);

    round_all<<<(NTOT4 + 255) / 256, 256>>>(Q_in, K_in, V_in, W_q, W_k, W_v, W_o,
                                            rQ, rK, rV, rWq, rWk, rWv, rWo);

    gemm_qkv<<<dim3(8, 64, 3), 256, GEMM_SMEM>>>(rQ, rK, rV, rWq, rWk, rWv, Qp, Kp, Vp);

    flash_tc<<<dim3(SEQ / 128, NHEAD, BATCH), 256, FLASH_SMEM>>>(Qp, Kp, Vp, Ct);

    gemm_tc<<<dim3(8, 64), 256, GEMM_SMEM>>>(Ct, rWo, out, 0);
}